// round 12
// baseline (speedup 1.0000x reference)
#include <cuda_runtime.h>
#include <math.h>

#define N_GENES 15135
#define BS 8
#define HID 64
#define NCMT 1000
#define HFC 128
#define NROWS (N_GENES * BS)       // 121080
#define FPN (BS * HID)             // 512 floats per node
#define E_MAX 262144
#define P_MAX 131072

// ------------------- scratch (static device globals; no runtime alloc) -----
__device__ float g_bufA[(size_t)N_GENES * FPN];   // 31 MB
__device__ float g_bufB[(size_t)N_GENES * FPN];   // 31 MB
__device__ float g_dinv[N_GENES];
__device__ int   g_cnt [N_GENES];
__device__ int   g_fill[N_GENES];
__device__ int   g_rowptr[N_GENES + 1];
__device__ int   g_csr_src [E_MAX];
__device__ float g_csr_norm[E_MAX];
__device__ int   g_cnt2 [NCMT];
__device__ int   g_fill2[NCMT];
__device__ int   g_rowptr2[NCMT + 1];
__device__ int   g_csr2_row[P_MAX];
__device__ float g_s[(size_t)NROWS];      // s[n*8+b], accumulated across 3 layers
__device__ float g_pool[NCMT * BS];       // pooled mean + fcb, [c*8+b]
__device__ float g_part[8 * BS * HFC];    // mlp1 partials [chunk][b][j]

// ------------------- setup: zero, parallel degrees, scans, fills ------------
__global__ void zero_kernel() {
    int i = blockIdx.x * blockDim.x + threadIdx.x;
    if (i < N_GENES) { g_cnt[i] = 0; g_fill[i] = 0; }
    if (i < NCMT)    { g_cnt2[i] = 0; g_fill2[i] = 0; }
}

__global__ void degrees_kernel(const int* __restrict__ ei, int E,
                               const int* __restrict__ pcol, int P) {
    int i = blockIdx.x * blockDim.x + threadIdx.x;
    if (i < E) atomicAdd(&g_cnt[ei[E + i]], 1);
    if (i < P) atomicAdd(&g_cnt2[pcol[i]], 1);
}

// block 0: gene prefix (+dinv) from g_cnt; block 1: community prefix
__global__ void scans_kernel() {
    __shared__ int sh[1024];
    int tid = threadIdx.x;
    if (blockIdx.x == 0) {
        int carry = 0;
        for (int base = 0; base < N_GENES; base += 1024) {
            int i = base + tid;
            int v = (i < N_GENES) ? g_cnt[i] : 0;
            if (i < N_GENES) g_dinv[i] = 1.0f / sqrtf((float)v + 1.0f);
            sh[tid] = v;
            __syncthreads();
            for (int off = 1; off < 1024; off <<= 1) {
                int t = (tid >= off) ? sh[tid - off] : 0;
                __syncthreads();
                sh[tid] += t;
                __syncthreads();
            }
            if (i < N_GENES) g_rowptr[i] = carry + sh[tid] - v;  // exclusive
            carry += sh[1023];
            __syncthreads();
        }
        if (tid == 0) g_rowptr[N_GENES] = carry;
    } else {
        int v = (tid < NCMT) ? g_cnt2[tid] : 0;
        sh[tid] = v;
        __syncthreads();
        for (int off = 1; off < 1024; off <<= 1) {
            int t = (tid >= off) ? sh[tid - off] : 0;
            __syncthreads();
            sh[tid] += t;
            __syncthreads();
        }
        if (tid < NCMT) g_rowptr2[tid] = sh[tid] - v;
        if (tid == NCMT - 1) g_rowptr2[NCMT] = sh[tid];
    }
}

__global__ void fills_kernel(const int* __restrict__ ei, int E,
                             const int* __restrict__ prow,
                             const int* __restrict__ pcol, int P) {
    int i = blockIdx.x * blockDim.x + threadIdx.x;
    if (i < E) {
        int src = ei[i];
        int dst = ei[E + i];
        int pos = g_rowptr[dst] + atomicAdd(&g_fill[dst], 1);
        g_csr_src[pos] = src;
        g_csr_norm[pos] = g_dinv[src] * g_dinv[dst];
    }
    if (i < P) {
        int c = pcol[i];
        int pos = g_rowptr2[c] + atomicAdd(&g_fill2[c], 1);
        g_csr2_row[pos] = prow[i];
    }
}

// ------------------- GEMM1: row-per-thread, W broadcast from smem -----------
__global__ void __launch_bounds__(256) gemm1_kernel(
        const float* __restrict__ in, const float* __restrict__ W,
        float* __restrict__ out) {
    __shared__ float sW[4096];
    int tid = threadIdx.x;
    for (int i = tid; i < 1024; i += 256)
        ((float4*)sW)[i] = ((const float4*)W)[i];
    __syncthreads();
    int r = blockIdx.x * 256 + tid;
    if (r >= NROWS) return;
    int nn = r >> 3, bb = r & 7;
    const float4* src = (const float4*)(in + ((size_t)bb * N_GENES + nn) * 64);
    float4 row[16];
#pragma unroll
    for (int i = 0; i < 16; i++) row[i] = src[i];
    float4* orow = (float4*)(out + (size_t)r * 64);
    const float4* wv = (const float4*)sW;       // wv[k*16 + f4]
    for (int f4 = 0; f4 < 16; f4++) {
        float4 s0 = make_float4(0.f, 0.f, 0.f, 0.f);
        float4 s1 = make_float4(0.f, 0.f, 0.f, 0.f);
#pragma unroll
        for (int k4 = 0; k4 < 16; k4++) {
            float4 a  = row[k4];
            float4 w0 = wv[(4 * k4 + 0) * 16 + f4];
            float4 w1 = wv[(4 * k4 + 1) * 16 + f4];
            float4 w2 = wv[(4 * k4 + 2) * 16 + f4];
            float4 w3 = wv[(4 * k4 + 3) * 16 + f4];
            s0.x += a.x * w0.x; s0.y += a.x * w0.y; s0.z += a.x * w0.z; s0.w += a.x * w0.w;
            s1.x += a.y * w1.x; s1.y += a.y * w1.y; s1.z += a.y * w1.z; s1.w += a.y * w1.w;
            s0.x += a.z * w2.x; s0.y += a.z * w2.y; s0.z += a.z * w2.z; s0.w += a.z * w2.w;
            s1.x += a.w * w3.x; s1.y += a.w * w3.y; s1.z += a.w * w3.z; s1.w += a.w * w3.w;
        }
        orow[f4] = make_float4(s0.x + s1.x, s0.y + s1.y, s0.z + s1.z, s0.w + s1.w);
    }
}

// ------------------- fused GCN aggregate + fc-dot + next-layer GEMM ----------
__global__ void __launch_bounds__(128) agg_fused_kernel(
        const float* __restrict__ h_in, const float* __restrict__ bias,
        const float* __restrict__ W_next, float* __restrict__ h_out,
        const float* __restrict__ fcW, int fc_off, int accum) {
    __shared__ float sX[512];
    __shared__ int   sSrc[128];
    __shared__ float sNrm[128];

    int n = blockIdx.x;
    int t = threadIdx.x;
    const float4* __restrict__ h4 = (const float4*)h_in;

    float dv = g_dinv[n];
    float4 acc = h4[(size_t)n * 128 + t];
    float w0 = dv * dv;
    acc.x *= w0; acc.y *= w0; acc.z *= w0; acc.w *= w0;
    float4 acc2 = make_float4(0.f, 0.f, 0.f, 0.f);

    int e0 = g_rowptr[n], e1 = g_rowptr[n + 1];
    for (int cs = e0; cs < e1; cs += 128) {
        int idx = cs + t;
        if (idx < e1) { sSrc[t] = g_csr_src[idx]; sNrm[t] = g_csr_norm[idx]; }
        __syncthreads();
        int m = e1 - cs; if (m > 128) m = 128;
        int j = 0;
        for (; j + 8 <= m; j += 8) {
            int   s0 = sSrc[j],     s1 = sSrc[j + 1];
            int   s2 = sSrc[j + 2], s3 = sSrc[j + 3];
            int   s4 = sSrc[j + 4], s5 = sSrc[j + 5];
            int   s6 = sSrc[j + 6], s7 = sSrc[j + 7];
            float u0 = sNrm[j],     u1 = sNrm[j + 1];
            float u2 = sNrm[j + 2], u3 = sNrm[j + 3];
            float u4 = sNrm[j + 4], u5 = sNrm[j + 5];
            float u6 = sNrm[j + 6], u7 = sNrm[j + 7];
            float4 v0 = h4[(size_t)s0 * 128 + t];
            float4 v1 = h4[(size_t)s1 * 128 + t];
            float4 v2 = h4[(size_t)s2 * 128 + t];
            float4 v3 = h4[(size_t)s3 * 128 + t];
            float4 v4 = h4[(size_t)s4 * 128 + t];
            float4 v5 = h4[(size_t)s5 * 128 + t];
            float4 v6 = h4[(size_t)s6 * 128 + t];
            float4 v7 = h4[(size_t)s7 * 128 + t];
            acc.x  += u0 * v0.x; acc.y  += u0 * v0.y; acc.z  += u0 * v0.z; acc.w  += u0 * v0.w;
            acc2.x += u1 * v1.x; acc2.y += u1 * v1.y; acc2.z += u1 * v1.z; acc2.w += u1 * v1.w;
            acc.x  += u2 * v2.x; acc.y  += u2 * v2.y; acc.z  += u2 * v2.z; acc.w  += u2 * v2.w;
            acc2.x += u3 * v3.x; acc2.y += u3 * v3.y; acc2.z += u3 * v3.z; acc2.w += u3 * v3.w;
            acc.x  += u4 * v4.x; acc.y  += u4 * v4.y; acc.z  += u4 * v4.z; acc.w  += u4 * v4.w;
            acc2.x += u5 * v5.x; acc2.y += u5 * v5.y; acc2.z += u5 * v5.z; acc2.w += u5 * v5.w;
            acc.x  += u6 * v6.x; acc.y  += u6 * v6.y; acc.z  += u6 * v6.z; acc.w  += u6 * v6.w;
            acc2.x += u7 * v7.x; acc2.y += u7 * v7.y; acc2.z += u7 * v7.z; acc2.w += u7 * v7.w;
        }
        for (; j < m; j++) {
            int s = sSrc[j];
            float u = sNrm[j];
            float4 v = h4[(size_t)s * 128 + t];
            acc.x += u * v.x; acc.y += u * v.y; acc.z += u * v.z; acc.w += u * v.w;
        }
        __syncthreads();
    }
    acc.x += acc2.x; acc.y += acc2.y; acc.z += acc2.z; acc.w += acc2.w;
    float4 bb = ((const float4*)bias)[t & 15];
    acc.x = fmaxf(acc.x + bb.x, 0.f);
    acc.y = fmaxf(acc.y + bb.y, 0.f);
    acc.z = fmaxf(acc.z + bb.z, 0.f);
    acc.w = fmaxf(acc.w + bb.w, 0.f);

    int ht = (t & 15) * 4;
    float sp = acc.x * fcW[3 * ht + fc_off]
             + acc.y * fcW[3 * (ht + 1) + fc_off]
             + acc.z * fcW[3 * (ht + 2) + fc_off]
             + acc.w * fcW[3 * (ht + 3) + fc_off];
#pragma unroll
    for (int off = 8; off; off >>= 1) sp += __shfl_xor_sync(0xffffffffu, sp, off);
    if ((t & 15) == 0) {
        size_t idx = (size_t)n * 8 + (t >> 4);
        g_s[idx] = accum ? (g_s[idx] + sp) : sp;
    }

    if (W_next) {
        ((float4*)sX)[t] = acc;
        __syncthreads();
        int b = t >> 4, q = t & 15;
        const float* xrow = sX + b * 64;
        const float4* Wv = (const float4*)W_next;    // Wv[k*16 + q]
        float4 o = make_float4(0.f, 0.f, 0.f, 0.f);
#pragma unroll 8
        for (int k = 0; k < 64; k++) {
            float a = xrow[k];
            float4 w = __ldg(Wv + k * 16 + q);
            o.x += a * w.x; o.y += a * w.y; o.z += a * w.z; o.w += a * w.w;
        }
        ((float4*)h_out)[(size_t)n * 128 + t] = o;
    }
}

// ------------------- pathway pooled mean via CSR (deterministic, double) ----
__global__ void __launch_bounds__(256) pool_kernel(const float* __restrict__ fcb) {
    __shared__ double sh[256];
    int c = blockIdx.x;
    int tid = threadIdx.x;
    int b = tid & 7;
    int i = tid >> 3;
    int e0 = g_rowptr2[c], e1 = g_rowptr2[c + 1];
    double acc = 0.0;
    for (int e = e0 + i; e < e1; e += 32) {
        int r = g_csr2_row[e];
        acc += (double)g_s[(size_t)r * 8 + b];
    }
    sh[tid] = acc;
    __syncthreads();
    for (int off = 128; off >= 8; off >>= 1) {
        if (tid < off) sh[tid] += sh[tid + off];
        __syncthreads();
    }
    if (tid < 8) {
        double cnt = (double)(e1 - e0);
        if (cnt < 1.0) cnt = 1.0;
        g_pool[c * 8 + tid] = (float)(sh[tid] / cnt + (double)fcb[0]);
    }
}

// ------------------- MLP head ------------------------------------------------
__global__ void __launch_bounds__(128) mlp1_kernel(const float* __restrict__ l1W) {
    int b = blockIdx.x & 7;
    int chunk = blockIdx.x >> 3;
    int j = threadIdx.x;
    int c0 = chunk * 125, c1 = c0 + 125;
    float acc = 0.f;
    for (int c = c0; c < c1; c++)
        acc += g_pool[c * 8 + b] * l1W[c * HFC + j];
    g_part[((size_t)chunk * 8 + b) * HFC + j] = acc;
}

__global__ void __launch_bounds__(128) mlp2_kernel(
        const float* __restrict__ l1b, const float* __restrict__ l2W,
        const float* __restrict__ l2b, float* __restrict__ out) {
    __shared__ double sz0[128], sz1[128];
    int b = blockIdx.x, j = threadIdx.x;
    double hv = (double)l1b[j];
#pragma unroll
    for (int k = 0; k < 8; k++) hv += (double)g_part[((size_t)k * 8 + b) * HFC + j];
    if (hv < 0.0) hv = 0.0;
    sz0[j] = hv * (double)l2W[j * 2];
    sz1[j] = hv * (double)l2W[j * 2 + 1];
    __syncthreads();
    for (int off = 64; off; off >>= 1) {
        if (j < off) { sz0[j] += sz0[j + off]; sz1[j] += sz1[j + off]; }
        __syncthreads();
    }
    if (j == 0) {
        double z0 = sz0[0] + (double)l2b[0];
        double z1 = sz1[0] + (double)l2b[1];
        double m = z0 > z1 ? z0 : z1;
        double lse = m + log(exp(z0 - m) + exp(z1 - m));
        out[b * 2]     = (float)(z0 - lse);
        out[b * 2 + 1] = (float)(z1 - lse);
    }
}

// ------------------- launch --------------------------------------------------
// PROBE ROUND: layer-1 agg (accum=0, idempotent) launched 3x. The two extra
// copies recompute identical values; (dur - base_band)/2 = one agg's true
// wall contribution. Histogram un-fused back to parallel global atomics.
extern "C" void kernel_launch(void* const* d_in, const int* in_sizes, int n_in,
                              void* d_out, int out_size) {
    const float* x    = (const float*)d_in[0];
    const int*   ei   = (const int*)  d_in[2];
    const int*   prow = (const int*)  d_in[3];
    const int*   pcol = (const int*)  d_in[4];
    const float* W1   = (const float*)d_in[5];
    const float* b1   = (const float*)d_in[6];
    const float* W2   = (const float*)d_in[7];
    const float* b2   = (const float*)d_in[8];
    const float* W3   = (const float*)d_in[9];
    const float* b3   = (const float*)d_in[10];
    const float* fcW  = (const float*)d_in[11];
    const float* fcb  = (const float*)d_in[12];
    const float* l1W  = (const float*)d_in[13];
    const float* l1b  = (const float*)d_in[14];
    const float* l2W  = (const float*)d_in[15];
    const float* l2b  = (const float*)d_in[16];
    float* out = (float*)d_out;

    int E = in_sizes[2] / 2;
    int P = in_sizes[3];
    int EP = E > P ? E : P;

    int g1_blocks = (NROWS + 255) / 256;                      // 473

    zero_kernel<<<(N_GENES + 255) / 256, 256>>>();
    degrees_kernel<<<(EP + 255) / 256, 256>>>(ei, E, pcol, P);
    scans_kernel<<<2, 1024>>>();
    gemm1_kernel<<<g1_blocks, 256>>>(x, W1, g_bufA);
    fills_kernel<<<(EP + 255) / 256, 256>>>(ei, E, prow, pcol, P);
    // --- probe: 3 identical, idempotent layer-1 aggs ---
    agg_fused_kernel<<<N_GENES, 128>>>(g_bufA, b1, W2, g_bufB, fcW, 0, 0);
    agg_fused_kernel<<<N_GENES, 128>>>(g_bufA, b1, W2, g_bufB, fcW, 0, 0);
    agg_fused_kernel<<<N_GENES, 128>>>(g_bufA, b1, W2, g_bufB, fcW, 0, 0);
    // ---------------------------------------------------
    agg_fused_kernel<<<N_GENES, 128>>>(g_bufB, b2, W3, g_bufA, fcW, 1, 1);
    agg_fused_kernel<<<N_GENES, 128>>>(g_bufA, b3, (const float*)0,
                                       (float*)0, fcW, 2, 1);
    pool_kernel<<<NCMT, 256>>>(fcb);
    mlp1_kernel<<<64, HFC>>>(l1W);
    mlp2_kernel<<<BS, HFC>>>(l1b, l2W, l2b, out);
}

// round 13
// speedup vs baseline: 1.6108x; 1.6108x over previous
#include <cuda_runtime.h>
#include <math.h>

#define N_GENES 15135
#define BS 8
#define HID 64
#define NCMT 1000
#define HFC 128
#define NROWS (N_GENES * BS)       // 121080
#define FPN (BS * HID)             // 512 floats per node
#define E_MAX 262144
#define P_MAX 131072

// ------------------- scratch (static device globals; no runtime alloc) -----
__device__ float g_bufA[(size_t)N_GENES * FPN];   // 31 MB
__device__ float g_bufB[(size_t)N_GENES * FPN];   // 31 MB
__device__ float g_dinv[N_GENES];
__device__ int   g_cnt [N_GENES];
__device__ int   g_fill[N_GENES];
__device__ int   g_rowptr[N_GENES + 1];
__device__ int   g_csr_src [E_MAX];
__device__ float g_csr_norm[E_MAX];
__device__ int   g_cnt2 [NCMT];
__device__ int   g_fill2[NCMT];
__device__ int   g_rowptr2[NCMT + 1];
__device__ int   g_csr2_row[P_MAX];
__device__ float g_s[(size_t)NROWS];      // s[n*8+b], accumulated across 3 layers
__device__ float g_pool[NCMT * BS];       // pooled mean + fcb, [c*8+b]
__device__ float g_part[8 * BS * HFC];    // mlp1 partials [chunk][b][j]

// ------------------- setup: zero, parallel degrees, scans, fills ------------
__global__ void zero_kernel() {
    int i = blockIdx.x * blockDim.x + threadIdx.x;
    if (i < N_GENES) { g_cnt[i] = 0; g_fill[i] = 0; }
    if (i < NCMT)    { g_cnt2[i] = 0; g_fill2[i] = 0; }
}

__global__ void degrees_kernel(const int* __restrict__ ei, int E,
                               const int* __restrict__ pcol, int P) {
    int i = blockIdx.x * blockDim.x + threadIdx.x;
    if (i < E) atomicAdd(&g_cnt[ei[E + i]], 1);
    if (i < P) atomicAdd(&g_cnt2[pcol[i]], 1);
}

__global__ void scans_kernel() {
    __shared__ int sh[1024];
    int tid = threadIdx.x;
    if (blockIdx.x == 0) {
        int carry = 0;
        for (int base = 0; base < N_GENES; base += 1024) {
            int i = base + tid;
            int v = (i < N_GENES) ? g_cnt[i] : 0;
            if (i < N_GENES) g_dinv[i] = 1.0f / sqrtf((float)v + 1.0f);
            sh[tid] = v;
            __syncthreads();
            for (int off = 1; off < 1024; off <<= 1) {
                int t = (tid >= off) ? sh[tid - off] : 0;
                __syncthreads();
                sh[tid] += t;
                __syncthreads();
            }
            if (i < N_GENES) g_rowptr[i] = carry + sh[tid] - v;  // exclusive
            carry += sh[1023];
            __syncthreads();
        }
        if (tid == 0) g_rowptr[N_GENES] = carry;
    } else {
        int v = (tid < NCMT) ? g_cnt2[tid] : 0;
        sh[tid] = v;
        __syncthreads();
        for (int off = 1; off < 1024; off <<= 1) {
            int t = (tid >= off) ? sh[tid - off] : 0;
            __syncthreads();
            sh[tid] += t;
            __syncthreads();
        }
        if (tid < NCMT) g_rowptr2[tid] = sh[tid] - v;
        if (tid == NCMT - 1) g_rowptr2[NCMT] = sh[tid];
    }
}

__global__ void fills_kernel(const int* __restrict__ ei, int E,
                             const int* __restrict__ prow,
                             const int* __restrict__ pcol, int P) {
    int i = blockIdx.x * blockDim.x + threadIdx.x;
    if (i < E) {
        int src = ei[i];
        int dst = ei[E + i];
        int pos = g_rowptr[dst] + atomicAdd(&g_fill[dst], 1);
        g_csr_src[pos] = src;
        g_csr_norm[pos] = g_dinv[src] * g_dinv[dst];
    }
    if (i < P) {
        int c = pcol[i];
        int pos = g_rowptr2[c] + atomicAdd(&g_fill2[c], 1);
        g_csr2_row[pos] = prow[i];
    }
}

// ------------------- GEMM (64x64 register tile, 4x4 per thread) --------------
// out[r*64+f] = sum_k in_row(r)[k] * W[k*64+f]
// layout==0: input is x [bs, N, 64], row r -> (n=r>>3, b=r&7)
// layout==1: input is [N, bs, 64] flat, row r contiguous
#define A_PAD 68
__global__ void __launch_bounds__(256) gemm_kernel(
        const float* __restrict__ in, const float* __restrict__ W,
        float* __restrict__ out, int layout) {
    __shared__ float sA[64][A_PAD];
    __shared__ float sW[64][64];
    int tid = threadIdx.x;
    int rbase = blockIdx.x * 64;
    for (int i = tid; i < 1024; i += 256) {
        int k = i >> 4, f4 = i & 15;
        ((float4*)&sW[k][0])[f4] = ((const float4*)W)[i];
    }
    for (int i = tid; i < 1024; i += 256) {
        int rr = i >> 4, c4 = i & 15;
        int grow = rbase + rr;
        float4 v = make_float4(0.f, 0.f, 0.f, 0.f);
        if (grow < NROWS) {
            const float* src;
            if (layout == 0) {
                int nn = grow >> 3, bb = grow & 7;
                src = in + ((size_t)bb * N_GENES + nn) * 64;
            } else {
                src = in + (size_t)grow * 64;
            }
            v = ((const float4*)src)[c4];
        }
        ((float4*)&sA[rr][0])[c4] = v;
    }
    __syncthreads();
    int tx = tid & 15, ty = tid >> 4;
    float acc[4][4];
#pragma unroll
    for (int i = 0; i < 4; i++)
#pragma unroll
        for (int j = 0; j < 4; j++) acc[i][j] = 0.f;
#pragma unroll 4
    for (int k = 0; k < 64; k++) {
        float4 b = *(const float4*)&sW[k][tx * 4];
        float a0 = sA[ty * 4 + 0][k];
        float a1 = sA[ty * 4 + 1][k];
        float a2 = sA[ty * 4 + 2][k];
        float a3 = sA[ty * 4 + 3][k];
        acc[0][0] += a0 * b.x; acc[0][1] += a0 * b.y; acc[0][2] += a0 * b.z; acc[0][3] += a0 * b.w;
        acc[1][0] += a1 * b.x; acc[1][1] += a1 * b.y; acc[1][2] += a1 * b.z; acc[1][3] += a1 * b.w;
        acc[2][0] += a2 * b.x; acc[2][1] += a2 * b.y; acc[2][2] += a2 * b.z; acc[2][3] += a2 * b.w;
        acc[3][0] += a3 * b.x; acc[3][1] += a3 * b.y; acc[3][2] += a3 * b.z; acc[3][3] += a3 * b.w;
    }
#pragma unroll
    for (int i = 0; i < 4; i++) {
        int grow = rbase + ty * 4 + i;
        if (grow < NROWS) {
            float4 o = make_float4(acc[i][0], acc[i][1], acc[i][2], acc[i][3]);
            ((float4*)&out[(size_t)grow * 64])[tx] = o;
        }
    }
}

// ------------------- pure GCN aggregate + fc-dot -----------------------------
// x = relu(sum_e w*h_in[src] + dinv^2*h_in[n] + bias)
// s[n,b] (+)= sum_h x[b,h] * fcW[3h + fc_off];  optionally store x (xout!=0)
__global__ void __launch_bounds__(128) agg_kernel(
        const float* __restrict__ h_in, const float* __restrict__ bias,
        float* __restrict__ xout, const float* __restrict__ fcW,
        int fc_off, int accum) {
    __shared__ int   sSrc[128];
    __shared__ float sNrm[128];

    int n = blockIdx.x;
    int t = threadIdx.x;
    const float4* __restrict__ h4 = (const float4*)h_in;

    float dv = g_dinv[n];
    float4 acc = h4[(size_t)n * 128 + t];
    float w0 = dv * dv;
    acc.x *= w0; acc.y *= w0; acc.z *= w0; acc.w *= w0;
    float4 acc2 = make_float4(0.f, 0.f, 0.f, 0.f);

    int e0 = g_rowptr[n], e1 = g_rowptr[n + 1];
    for (int cs = e0; cs < e1; cs += 128) {
        int idx = cs + t;
        if (idx < e1) { sSrc[t] = g_csr_src[idx]; sNrm[t] = g_csr_norm[idx]; }
        __syncthreads();
        int m = e1 - cs; if (m > 128) m = 128;
        int j = 0;
        for (; j + 8 <= m; j += 8) {
            int   s0 = sSrc[j],     s1 = sSrc[j + 1];
            int   s2 = sSrc[j + 2], s3 = sSrc[j + 3];
            int   s4 = sSrc[j + 4], s5 = sSrc[j + 5];
            int   s6 = sSrc[j + 6], s7 = sSrc[j + 7];
            float u0 = sNrm[j],     u1 = sNrm[j + 1];
            float u2 = sNrm[j + 2], u3 = sNrm[j + 3];
            float u4 = sNrm[j + 4], u5 = sNrm[j + 5];
            float u6 = sNrm[j + 6], u7 = sNrm[j + 7];
            float4 v0 = h4[(size_t)s0 * 128 + t];
            float4 v1 = h4[(size_t)s1 * 128 + t];
            float4 v2 = h4[(size_t)s2 * 128 + t];
            float4 v3 = h4[(size_t)s3 * 128 + t];
            float4 v4 = h4[(size_t)s4 * 128 + t];
            float4 v5 = h4[(size_t)s5 * 128 + t];
            float4 v6 = h4[(size_t)s6 * 128 + t];
            float4 v7 = h4[(size_t)s7 * 128 + t];
            acc.x  += u0 * v0.x; acc.y  += u0 * v0.y; acc.z  += u0 * v0.z; acc.w  += u0 * v0.w;
            acc2.x += u1 * v1.x; acc2.y += u1 * v1.y; acc2.z += u1 * v1.z; acc2.w += u1 * v1.w;
            acc.x  += u2 * v2.x; acc.y  += u2 * v2.y; acc.z  += u2 * v2.z; acc.w  += u2 * v2.w;
            acc2.x += u3 * v3.x; acc2.y += u3 * v3.y; acc2.z += u3 * v3.z; acc2.w += u3 * v3.w;
            acc.x  += u4 * v4.x; acc.y  += u4 * v4.y; acc.z  += u4 * v4.z; acc.w  += u4 * v4.w;
            acc2.x += u5 * v5.x; acc2.y += u5 * v5.y; acc2.z += u5 * v5.z; acc2.w += u5 * v5.w;
            acc.x  += u6 * v6.x; acc.y  += u6 * v6.y; acc.z  += u6 * v6.z; acc.w  += u6 * v6.w;
            acc2.x += u7 * v7.x; acc2.y += u7 * v7.y; acc2.z += u7 * v7.z; acc2.w += u7 * v7.w;
        }
        for (; j < m; j++) {
            int s = sSrc[j];
            float u = sNrm[j];
            float4 v = h4[(size_t)s * 128 + t];
            acc.x += u * v.x; acc.y += u * v.y; acc.z += u * v.z; acc.w += u * v.w;
        }
        __syncthreads();
    }
    acc.x += acc2.x; acc.y += acc2.y; acc.z += acc2.z; acc.w += acc2.w;
    float4 bb = ((const float4*)bias)[t & 15];
    acc.x = fmaxf(acc.x + bb.x, 0.f);
    acc.y = fmaxf(acc.y + bb.y, 0.f);
    acc.z = fmaxf(acc.z + bb.z, 0.f);
    acc.w = fmaxf(acc.w + bb.w, 0.f);

    // fc-dot contribution
    int ht = (t & 15) * 4;
    float sp = acc.x * fcW[3 * ht + fc_off]
             + acc.y * fcW[3 * (ht + 1) + fc_off]
             + acc.z * fcW[3 * (ht + 2) + fc_off]
             + acc.w * fcW[3 * (ht + 3) + fc_off];
#pragma unroll
    for (int off = 8; off; off >>= 1) sp += __shfl_xor_sync(0xffffffffu, sp, off);
    if ((t & 15) == 0) {
        size_t idx = (size_t)n * 8 + (t >> 4);
        g_s[idx] = accum ? (g_s[idx] + sp) : sp;
    }

    if (xout) ((float4*)xout)[(size_t)n * 128 + t] = acc;
}

// ------------------- pathway pooled mean via CSR (deterministic, double) ----
__global__ void __launch_bounds__(256) pool_kernel(const float* __restrict__ fcb) {
    __shared__ double sh[256];
    int c = blockIdx.x;
    int tid = threadIdx.x;
    int b = tid & 7;
    int i = tid >> 3;
    int e0 = g_rowptr2[c], e1 = g_rowptr2[c + 1];
    double acc = 0.0;
    for (int e = e0 + i; e < e1; e += 32) {
        int r = g_csr2_row[e];
        acc += (double)g_s[(size_t)r * 8 + b];
    }
    sh[tid] = acc;
    __syncthreads();
    for (int off = 128; off >= 8; off >>= 1) {
        if (tid < off) sh[tid] += sh[tid + off];
        __syncthreads();
    }
    if (tid < 8) {
        double cnt = (double)(e1 - e0);
        if (cnt < 1.0) cnt = 1.0;
        g_pool[c * 8 + tid] = (float)(sh[tid] / cnt + (double)fcb[0]);
    }
}

// ------------------- MLP head ------------------------------------------------
__global__ void __launch_bounds__(128) mlp1_kernel(const float* __restrict__ l1W) {
    int b = blockIdx.x & 7;
    int chunk = blockIdx.x >> 3;
    int j = threadIdx.x;
    int c0 = chunk * 125, c1 = c0 + 125;
    float acc = 0.f;
    for (int c = c0; c < c1; c++)
        acc += g_pool[c * 8 + b] * l1W[c * HFC + j];
    g_part[((size_t)chunk * 8 + b) * HFC + j] = acc;
}

__global__ void __launch_bounds__(128) mlp2_kernel(
        const float* __restrict__ l1b, const float* __restrict__ l2W,
        const float* __restrict__ l2b, float* __restrict__ out) {
    __shared__ double sz0[128], sz1[128];
    int b = blockIdx.x, j = threadIdx.x;
    double hv = (double)l1b[j];
#pragma unroll
    for (int k = 0; k < 8; k++) hv += (double)g_part[((size_t)k * 8 + b) * HFC + j];
    if (hv < 0.0) hv = 0.0;
    sz0[j] = hv * (double)l2W[j * 2];
    sz1[j] = hv * (double)l2W[j * 2 + 1];
    __syncthreads();
    for (int off = 64; off; off >>= 1) {
        if (j < off) { sz0[j] += sz0[j + off]; sz1[j] += sz1[j + off]; }
        __syncthreads();
    }
    if (j == 0) {
        double z0 = sz0[0] + (double)l2b[0];
        double z1 = sz1[0] + (double)l2b[1];
        double m = z0 > z1 ? z0 : z1;
        double lse = m + log(exp(z0 - m) + exp(z1 - m));
        out[b * 2]     = (float)(z0 - lse);
        out[b * 2 + 1] = (float)(z1 - lse);
    }
}

// ------------------- launch --------------------------------------------------
extern "C" void kernel_launch(void* const* d_in, const int* in_sizes, int n_in,
                              void* d_out, int out_size) {
    const float* x    = (const float*)d_in[0];
    const int*   ei   = (const int*)  d_in[2];
    const int*   prow = (const int*)  d_in[3];
    const int*   pcol = (const int*)  d_in[4];
    const float* W1   = (const float*)d_in[5];
    const float* b1   = (const float*)d_in[6];
    const float* W2   = (const float*)d_in[7];
    const float* b2   = (const float*)d_in[8];
    const float* W3   = (const float*)d_in[9];
    const float* b3   = (const float*)d_in[10];
    const float* fcW  = (const float*)d_in[11];
    const float* fcb  = (const float*)d_in[12];
    const float* l1W  = (const float*)d_in[13];
    const float* l1b  = (const float*)d_in[14];
    const float* l2W  = (const float*)d_in[15];
    const float* l2b  = (const float*)d_in[16];
    float* out = (float*)d_out;

    int E = in_sizes[2] / 2;
    int P = in_sizes[3];
    int EP = E > P ? E : P;

    int gemm_blocks = (NROWS + 63) / 64;                      // 1892

    // launch order (ncu captures idx 3 = gemm1):
    zero_kernel<<<(N_GENES + 255) / 256, 256>>>();                         // 0
    degrees_kernel<<<(EP + 255) / 256, 256>>>(ei, E, pcol, P);             // 1
    scans_kernel<<<2, 1024>>>();                                           // 2
    gemm_kernel<<<gemm_blocks, 256>>>(x, W1, g_bufA, 0);                   // 3 <- profiled
    fills_kernel<<<(EP + 255) / 256, 256>>>(ei, E, prow, pcol, P);         // 4
    agg_kernel<<<N_GENES, 128>>>(g_bufA, b1, g_bufB, fcW, 0, 0);           // 5
    gemm_kernel<<<gemm_blocks, 256>>>(g_bufB, W2, g_bufA, 1);              // 6
    agg_kernel<<<N_GENES, 128>>>(g_bufA, b2, g_bufB, fcW, 1, 1);           // 7
    gemm_kernel<<<gemm_blocks, 256>>>(g_bufB, W3, g_bufA, 1);              // 8
    agg_kernel<<<N_GENES, 128>>>(g_bufA, b3, (float*)0, fcW, 2, 1);        // 9
    pool_kernel<<<NCMT, 256>>>(fcb);                                       // 10
    mlp1_kernel<<<64, HFC>>>(l1W);                                         // 11
    mlp2_kernel<<<BS, HFC>>>(l1b, l2W, l2b, out);                          // 12
}

// round 14
// speedup vs baseline: 2.9584x; 1.8366x over previous
#include <cuda_runtime.h>
#include <cuda_fp16.h>
#include <math.h>

#define N_GENES 15135
#define BS 8
#define HID 64
#define NCMT 1000
#define HFC 128
#define NROWS (N_GENES * BS)       // 121080
#define FPN (BS * HID)             // 512 floats per node
#define E_MAX 262144
#define P_MAX 131072

// ------------------- scratch (static device globals; no runtime alloc) -----
__device__ __half g_h16[(size_t)N_GENES * FPN];   // 15.5 MB (gathered operand)
__device__ float  g_x  [(size_t)N_GENES * FPN];   // 31 MB (post-relu, fp32)
__device__ float g_dinv[N_GENES];
__device__ int   g_cnt [N_GENES];
__device__ int   g_fill[N_GENES];
__device__ int   g_rowptr[N_GENES + 1];
__device__ int   g_csr_src [E_MAX];
__device__ float g_csr_norm[E_MAX];
__device__ int   g_cnt2 [NCMT];
__device__ int   g_fill2[NCMT];
__device__ int   g_rowptr2[NCMT + 1];
__device__ int   g_csr2_row[P_MAX];
__device__ float g_s[(size_t)NROWS];      // s[n*8+b], accumulated across 3 layers
__device__ float g_pool[NCMT * BS];       // pooled mean + fcb, [c*8+b]
__device__ float g_part[8 * BS * HFC];    // mlp1 partials [chunk][b][j]

union Half4 { uint2 u; __half2 h[2]; };

// ------------------- setup: zero, parallel degrees, scans, fills ------------
__global__ void zero_kernel() {
    int i = blockIdx.x * blockDim.x + threadIdx.x;
    if (i < N_GENES) { g_cnt[i] = 0; g_fill[i] = 0; }
    if (i < NCMT)    { g_cnt2[i] = 0; g_fill2[i] = 0; }
}

__global__ void degrees_kernel(const int* __restrict__ ei, int E,
                               const int* __restrict__ pcol, int P) {
    int i = blockIdx.x * blockDim.x + threadIdx.x;
    if (i < E) atomicAdd(&g_cnt[ei[E + i]], 1);
    if (i < P) atomicAdd(&g_cnt2[pcol[i]], 1);
}

__global__ void scans_kernel() {
    __shared__ int sh[1024];
    int tid = threadIdx.x;
    if (blockIdx.x == 0) {
        int carry = 0;
        for (int base = 0; base < N_GENES; base += 1024) {
            int i = base + tid;
            int v = (i < N_GENES) ? g_cnt[i] : 0;
            if (i < N_GENES) g_dinv[i] = 1.0f / sqrtf((float)v + 1.0f);
            sh[tid] = v;
            __syncthreads();
            for (int off = 1; off < 1024; off <<= 1) {
                int t = (tid >= off) ? sh[tid - off] : 0;
                __syncthreads();
                sh[tid] += t;
                __syncthreads();
            }
            if (i < N_GENES) g_rowptr[i] = carry + sh[tid] - v;  // exclusive
            carry += sh[1023];
            __syncthreads();
        }
        if (tid == 0) g_rowptr[N_GENES] = carry;
    } else {
        int v = (tid < NCMT) ? g_cnt2[tid] : 0;
        sh[tid] = v;
        __syncthreads();
        for (int off = 1; off < 1024; off <<= 1) {
            int t = (tid >= off) ? sh[tid - off] : 0;
            __syncthreads();
            sh[tid] += t;
            __syncthreads();
        }
        if (tid < NCMT) g_rowptr2[tid] = sh[tid] - v;
        if (tid == NCMT - 1) g_rowptr2[NCMT] = sh[tid];
    }
}

__global__ void fills_kernel(const int* __restrict__ ei, int E,
                             const int* __restrict__ prow,
                             const int* __restrict__ pcol, int P) {
    int i = blockIdx.x * blockDim.x + threadIdx.x;
    if (i < E) {
        int src = ei[i];
        int dst = ei[E + i];
        int pos = g_rowptr[dst] + atomicAdd(&g_fill[dst], 1);
        g_csr_src[pos] = src;
        g_csr_norm[pos] = g_dinv[src] * g_dinv[dst];
    }
    if (i < P) {
        int c = pcol[i];
        int pos = g_rowptr2[c] + atomicAdd(&g_fill2[c], 1);
        g_csr2_row[pos] = prow[i];
    }
}

// ------------------- GEMM (64x64 register tile, 4x4 per thread) --------------
// h16[r*64+f] = (half) sum_k in_row(r)[k] * W[k*64+f]
// layout==0: input is x [bs, N, 64] fp32, row r -> (n=r>>3, b=r&7)
// layout==1: input is g_x [N*8, 64] fp32, row r contiguous
#define A_PAD 68
__global__ void __launch_bounds__(256) gemm_kernel(
        const float* __restrict__ in, const float* __restrict__ W,
        __half* __restrict__ out16, int layout) {
    __shared__ float sA[64][A_PAD];
    __shared__ float sW[64][64];
    int tid = threadIdx.x;
    int rbase = blockIdx.x * 64;
    for (int i = tid; i < 1024; i += 256) {
        int k = i >> 4, f4 = i & 15;
        ((float4*)&sW[k][0])[f4] = ((const float4*)W)[i];
    }
    for (int i = tid; i < 1024; i += 256) {
        int rr = i >> 4, c4 = i & 15;
        int grow = rbase + rr;
        float4 v = make_float4(0.f, 0.f, 0.f, 0.f);
        if (grow < NROWS) {
            const float* src;
            if (layout == 0) {
                int nn = grow >> 3, bb = grow & 7;
                src = in + ((size_t)bb * N_GENES + nn) * 64;
            } else {
                src = in + (size_t)grow * 64;
            }
            v = ((const float4*)src)[c4];
        }
        ((float4*)&sA[rr][0])[c4] = v;
    }
    __syncthreads();
    int tx = tid & 15, ty = tid >> 4;
    float acc[4][4];
#pragma unroll
    for (int i = 0; i < 4; i++)
#pragma unroll
        for (int j = 0; j < 4; j++) acc[i][j] = 0.f;
#pragma unroll 4
    for (int k = 0; k < 64; k++) {
        float4 b = *(const float4*)&sW[k][tx * 4];
        float a0 = sA[ty * 4 + 0][k];
        float a1 = sA[ty * 4 + 1][k];
        float a2 = sA[ty * 4 + 2][k];
        float a3 = sA[ty * 4 + 3][k];
        acc[0][0] += a0 * b.x; acc[0][1] += a0 * b.y; acc[0][2] += a0 * b.z; acc[0][3] += a0 * b.w;
        acc[1][0] += a1 * b.x; acc[1][1] += a1 * b.y; acc[1][2] += a1 * b.z; acc[1][3] += a1 * b.w;
        acc[2][0] += a2 * b.x; acc[2][1] += a2 * b.y; acc[2][2] += a2 * b.z; acc[2][3] += a2 * b.w;
        acc[3][0] += a3 * b.x; acc[3][1] += a3 * b.y; acc[3][2] += a3 * b.z; acc[3][3] += a3 * b.w;
    }
#pragma unroll
    for (int i = 0; i < 4; i++) {
        int grow = rbase + ty * 4 + i;
        if (grow < NROWS) {
            Half4 pk;
            pk.h[0] = __floats2half2_rn(acc[i][0], acc[i][1]);
            pk.h[1] = __floats2half2_rn(acc[i][2], acc[i][3]);
            ((uint2*)out16)[(size_t)grow * 16 + tx] = pk.u;   // row = 64 half = 16 uint2
        }
    }
}

// ------------------- pure GCN aggregate + fc-dot (fp16 gather, fp32 math) ----
// x = relu(sum_e w*h16[src] + dinv^2*h16[n] + bias)
// s[n,b] (+)= sum_h x[b,h] * fcW[3h + fc_off];  optionally store x fp32
__global__ void __launch_bounds__(128) agg_kernel(
        const __half* __restrict__ h16, const float* __restrict__ bias,
        float* __restrict__ xout, const float* __restrict__ fcW,
        int fc_off, int accum) {
    __shared__ int   sSrc[128];
    __shared__ float sNrm[128];

    int n = blockIdx.x;
    int t = threadIdx.x;                       // handles halfs 4t..4t+3 (uint2 lane t)
    const uint2* __restrict__ h4 = (const uint2*)h16;   // row = 128 uint2

    float dv = g_dinv[n];
    Half4 own; own.u = h4[(size_t)n * 128 + t];
    float2 o0 = __half22float2(own.h[0]);
    float2 o1 = __half22float2(own.h[1]);
    float w0 = dv * dv;
    float4 acc  = make_float4(o0.x * w0, o0.y * w0, o1.x * w0, o1.y * w0);
    float4 acc2 = make_float4(0.f, 0.f, 0.f, 0.f);

    int e0 = g_rowptr[n], e1 = g_rowptr[n + 1];
    for (int cs = e0; cs < e1; cs += 128) {
        int idx = cs + t;
        if (idx < e1) { sSrc[t] = g_csr_src[idx]; sNrm[t] = g_csr_norm[idx]; }
        __syncthreads();
        int m = e1 - cs; if (m > 128) m = 128;
        int j = 0;
        for (; j + 8 <= m; j += 8) {
            Half4 r0, r1, r2, r3, r4, r5, r6, r7;
            float u0 = sNrm[j],     u1 = sNrm[j + 1];
            float u2 = sNrm[j + 2], u3 = sNrm[j + 3];
            float u4 = sNrm[j + 4], u5 = sNrm[j + 5];
            float u6 = sNrm[j + 6], u7 = sNrm[j + 7];
            r0.u = h4[(size_t)sSrc[j]     * 128 + t];
            r1.u = h4[(size_t)sSrc[j + 1] * 128 + t];
            r2.u = h4[(size_t)sSrc[j + 2] * 128 + t];
            r3.u = h4[(size_t)sSrc[j + 3] * 128 + t];
            r4.u = h4[(size_t)sSrc[j + 4] * 128 + t];
            r5.u = h4[(size_t)sSrc[j + 5] * 128 + t];
            r6.u = h4[(size_t)sSrc[j + 6] * 128 + t];
            r7.u = h4[(size_t)sSrc[j + 7] * 128 + t];
            float2 a, b;
            a = __half22float2(r0.h[0]); b = __half22float2(r0.h[1]);
            acc.x  += u0 * a.x; acc.y  += u0 * a.y; acc.z  += u0 * b.x; acc.w  += u0 * b.y;
            a = __half22float2(r1.h[0]); b = __half22float2(r1.h[1]);
            acc2.x += u1 * a.x; acc2.y += u1 * a.y; acc2.z += u1 * b.x; acc2.w += u1 * b.y;
            a = __half22float2(r2.h[0]); b = __half22float2(r2.h[1]);
            acc.x  += u2 * a.x; acc.y  += u2 * a.y; acc.z  += u2 * b.x; acc.w  += u2 * b.y;
            a = __half22float2(r3.h[0]); b = __half22float2(r3.h[1]);
            acc2.x += u3 * a.x; acc2.y += u3 * a.y; acc2.z += u3 * b.x; acc2.w += u3 * b.y;
            a = __half22float2(r4.h[0]); b = __half22float2(r4.h[1]);
            acc.x  += u4 * a.x; acc.y  += u4 * a.y; acc.z  += u4 * b.x; acc.w  += u4 * b.y;
            a = __half22float2(r5.h[0]); b = __half22float2(r5.h[1]);
            acc2.x += u5 * a.x; acc2.y += u5 * a.y; acc2.z += u5 * b.x; acc2.w += u5 * b.y;
            a = __half22float2(r6.h[0]); b = __half22float2(r6.h[1]);
            acc.x  += u6 * a.x; acc.y  += u6 * a.y; acc.z  += u6 * b.x; acc.w  += u6 * b.y;
            a = __half22float2(r7.h[0]); b = __half22float2(r7.h[1]);
            acc2.x += u7 * a.x; acc2.y += u7 * a.y; acc2.z += u7 * b.x; acc2.w += u7 * b.y;
        }
        for (; j < m; j++) {
            float u = sNrm[j];
            Half4 r; r.u = h4[(size_t)sSrc[j] * 128 + t];
            float2 a = __half22float2(r.h[0]);
            float2 b = __half22float2(r.h[1]);
            acc.x += u * a.x; acc.y += u * a.y; acc.z += u * b.x; acc.w += u * b.y;
        }
        __syncthreads();
    }
    acc.x += acc2.x; acc.y += acc2.y; acc.z += acc2.z; acc.w += acc2.w;
    float4 bb = ((const float4*)bias)[t & 15];
    acc.x = fmaxf(acc.x + bb.x, 0.f);
    acc.y = fmaxf(acc.y + bb.y, 0.f);
    acc.z = fmaxf(acc.z + bb.z, 0.f);
    acc.w = fmaxf(acc.w + bb.w, 0.f);

    // fc-dot contribution (fp32)
    int ht = (t & 15) * 4;
    float sp = acc.x * fcW[3 * ht + fc_off]
             + acc.y * fcW[3 * (ht + 1) + fc_off]
             + acc.z * fcW[3 * (ht + 2) + fc_off]
             + acc.w * fcW[3 * (ht + 3) + fc_off];
#pragma unroll
    for (int off = 8; off; off >>= 1) sp += __shfl_xor_sync(0xffffffffu, sp, off);
    if ((t & 15) == 0) {
        size_t idx = (size_t)n * 8 + (t >> 4);
        g_s[idx] = accum ? (g_s[idx] + sp) : sp;
    }

    if (xout) ((float4*)xout)[(size_t)n * 128 + t] = acc;
}

// ------------------- pathway pooled mean via CSR (deterministic, double) ----
__global__ void __launch_bounds__(256) pool_kernel(const float* __restrict__ fcb) {
    __shared__ double sh[256];
    int c = blockIdx.x;
    int tid = threadIdx.x;
    int b = tid & 7;
    int i = tid >> 3;
    int e0 = g_rowptr2[c], e1 = g_rowptr2[c + 1];
    double acc = 0.0;
    for (int e = e0 + i; e < e1; e += 32) {
        int r = g_csr2_row[e];
        acc += (double)g_s[(size_t)r * 8 + b];
    }
    sh[tid] = acc;
    __syncthreads();
    for (int off = 128; off >= 8; off >>= 1) {
        if (tid < off) sh[tid] += sh[tid + off];
        __syncthreads();
    }
    if (tid < 8) {
        double cnt = (double)(e1 - e0);
        if (cnt < 1.0) cnt = 1.0;
        g_pool[c * 8 + tid] = (float)(sh[tid] / cnt + (double)fcb[0]);
    }
}

// ------------------- MLP head ------------------------------------------------
__global__ void __launch_bounds__(128) mlp1_kernel(const float* __restrict__ l1W) {
    int b = blockIdx.x & 7;
    int chunk = blockIdx.x >> 3;
    int j = threadIdx.x;
    int c0 = chunk * 125, c1 = c0 + 125;
    float acc = 0.f;
    for (int c = c0; c < c1; c++)
        acc += g_pool[c * 8 + b] * l1W[c * HFC + j];
    g_part[((size_t)chunk * 8 + b) * HFC + j] = acc;
}

__global__ void __launch_bounds__(128) mlp2_kernel(
        const float* __restrict__ l1b, const float* __restrict__ l2W,
        const float* __restrict__ l2b, float* __restrict__ out) {
    __shared__ double sz0[128], sz1[128];
    int b = blockIdx.x, j = threadIdx.x;
    double hv = (double)l1b[j];
#pragma unroll
    for (int k = 0; k < 8; k++) hv += (double)g_part[((size_t)k * 8 + b) * HFC + j];
    if (hv < 0.0) hv = 0.0;
    sz0[j] = hv * (double)l2W[j * 2];
    sz1[j] = hv * (double)l2W[j * 2 + 1];
    __syncthreads();
    for (int off = 64; off; off >>= 1) {
        if (j < off) { sz0[j] += sz0[j + off]; sz1[j] += sz1[j + off]; }
        __syncthreads();
    }
    if (j == 0) {
        double z0 = sz0[0] + (double)l2b[0];
        double z1 = sz1[0] + (double)l2b[1];
        double m = z0 > z1 ? z0 : z1;
        double lse = m + log(exp(z0 - m) + exp(z1 - m));
        out[b * 2]     = (float)(z0 - lse);
        out[b * 2 + 1] = (float)(z1 - lse);
    }
}

// ------------------- launch --------------------------------------------------
extern "C" void kernel_launch(void* const* d_in, const int* in_sizes, int n_in,
                              void* d_out, int out_size) {
    const float* x    = (const float*)d_in[0];
    const int*   ei   = (const int*)  d_in[2];
    const int*   prow = (const int*)  d_in[3];
    const int*   pcol = (const int*)  d_in[4];
    const float* W1   = (const float*)d_in[5];
    const float* b1   = (const float*)d_in[6];
    const float* W2   = (const float*)d_in[7];
    const float* b2   = (const float*)d_in[8];
    const float* W3   = (const float*)d_in[9];
    const float* b3   = (const float*)d_in[10];
    const float* fcW  = (const float*)d_in[11];
    const float* fcb  = (const float*)d_in[12];
    const float* l1W  = (const float*)d_in[13];
    const float* l1b  = (const float*)d_in[14];
    const float* l2W  = (const float*)d_in[15];
    const float* l2b  = (const float*)d_in[16];
    float* out = (float*)d_out;

    int E = in_sizes[2] / 2;
    int P = in_sizes[3];
    int EP = E > P ? E : P;

    int gemm_blocks = (NROWS + 63) / 64;                      // 1892

    // launch order (ncu captures idx 3 = gemm1):
    zero_kernel<<<(N_GENES + 255) / 256, 256>>>();                         // 0
    degrees_kernel<<<(EP + 255) / 256, 256>>>(ei, E, pcol, P);             // 1
    scans_kernel<<<2, 1024>>>();                                           // 2
    gemm_kernel<<<gemm_blocks, 256>>>(x, W1, g_h16, 0);                    // 3 <- profiled
    fills_kernel<<<(EP + 255) / 256, 256>>>(ei, E, prow, pcol, P);         // 4
    agg_kernel<<<N_GENES, 128>>>(g_h16, b1, g_x, fcW, 0, 0);               // 5
    gemm_kernel<<<gemm_blocks, 256>>>(g_x, W2, g_h16, 1);                  // 6
    agg_kernel<<<N_GENES, 128>>>(g_h16, b2, g_x, fcW, 1, 1);               // 7
    gemm_kernel<<<gemm_blocks, 256>>>(g_x, W3, g_h16, 1);                  // 8
    agg_kernel<<<N_GENES, 128>>>(g_h16, b3, (float*)0, fcW, 2, 1);         // 9
    pool_kernel<<<NCMT, 256>>>(fcb);                                       // 10
    mlp1_kernel<<<64, HFC>>>(l1W);                                         // 11
    mlp2_kernel<<<BS, HFC>>>(l1b, l2W, l2b, out);                          // 12
}

// round 15
// speedup vs baseline: 3.1262x; 1.0567x over previous
#include <cuda_runtime.h>
#include <cuda_fp16.h>
#include <math.h>

#define N_GENES 15135
#define BS 8
#define HID 64
#define NCMT 1000
#define HFC 128
#define NROWS (N_GENES * BS)       // 121080
#define FPN (BS * HID)             // 512 halfs per node
#define E_MAX 262144
#define P_MAX 131072

// ------------------- scratch (static device globals; no runtime alloc) -----
__device__ __half g_h16[(size_t)N_GENES * FPN];   // 15.5 MB (gathered operand)
__device__ __half g_x16[(size_t)N_GENES * FPN];   // 15.5 MB (post-relu x)
__device__ float g_dinv[N_GENES];
__device__ int   g_cnt [N_GENES];
__device__ int   g_fill[N_GENES];
__device__ int   g_rowptr[N_GENES + 1];
__device__ int   g_csr_src [E_MAX];
__device__ float g_csr_norm[E_MAX];
__device__ int   g_cnt2 [NCMT];
__device__ int   g_fill2[NCMT];
__device__ int   g_rowptr2[NCMT + 1];
__device__ int   g_csr2_row[P_MAX];
__device__ float g_s[(size_t)NROWS];      // s[n*8+b], accumulated across 3 layers
__device__ float g_pool[NCMT * BS];       // pooled mean + fcb, [c*8+b]
__device__ float g_part[8 * BS * HFC];    // mlp1 partials [chunk][b][j]

union Half4 { uint2 u; __half2 h[2]; };
union Half8 { uint4 u; __half2 h[4]; };

// ------------------- setup: zero, parallel degrees, scans, fills ------------
__global__ void zero_kernel() {
    int i = blockIdx.x * blockDim.x + threadIdx.x;
    if (i < N_GENES) { g_cnt[i] = 0; g_fill[i] = 0; }
    if (i < NCMT)    { g_cnt2[i] = 0; g_fill2[i] = 0; }
}

__global__ void degrees_kernel(const int* __restrict__ ei, int E,
                               const int* __restrict__ pcol, int P) {
    int i = blockIdx.x * blockDim.x + threadIdx.x;
    if (i < E) atomicAdd(&g_cnt[ei[E + i]], 1);
    if (i < P) atomicAdd(&g_cnt2[pcol[i]], 1);
}

__global__ void scans_kernel() {
    __shared__ int sh[1024];
    int tid = threadIdx.x;
    if (blockIdx.x == 0) {
        int carry = 0;
        for (int base = 0; base < N_GENES; base += 1024) {
            int i = base + tid;
            int v = (i < N_GENES) ? g_cnt[i] : 0;
            if (i < N_GENES) g_dinv[i] = 1.0f / sqrtf((float)v + 1.0f);
            sh[tid] = v;
            __syncthreads();
            for (int off = 1; off < 1024; off <<= 1) {
                int t = (tid >= off) ? sh[tid - off] : 0;
                __syncthreads();
                sh[tid] += t;
                __syncthreads();
            }
            if (i < N_GENES) g_rowptr[i] = carry + sh[tid] - v;  // exclusive
            carry += sh[1023];
            __syncthreads();
        }
        if (tid == 0) g_rowptr[N_GENES] = carry;
    } else {
        int v = (tid < NCMT) ? g_cnt2[tid] : 0;
        sh[tid] = v;
        __syncthreads();
        for (int off = 1; off < 1024; off <<= 1) {
            int t = (tid >= off) ? sh[tid - off] : 0;
            __syncthreads();
            sh[tid] += t;
            __syncthreads();
        }
        if (tid < NCMT) g_rowptr2[tid] = sh[tid] - v;
        if (tid == NCMT - 1) g_rowptr2[NCMT] = sh[tid];
    }
}

__global__ void fills_kernel(const int* __restrict__ ei, int E,
                             const int* __restrict__ prow,
                             const int* __restrict__ pcol, int P) {
    int i = blockIdx.x * blockDim.x + threadIdx.x;
    if (i < E) {
        int src = ei[i];
        int dst = ei[E + i];
        int pos = g_rowptr[dst] + atomicAdd(&g_fill[dst], 1);
        g_csr_src[pos] = src;
        g_csr_norm[pos] = g_dinv[src] * g_dinv[dst];
    }
    if (i < P) {
        int c = pcol[i];
        int pos = g_rowptr2[c] + atomicAdd(&g_fill2[c], 1);
        g_csr2_row[pos] = prow[i];
    }
}

// ------------------- GEMM (64x64 register tile, 4x4 per thread) --------------
// h16[r*64+f] = (half) sum_k in_row(r)[k] * W[k*64+f]
// layout==0: input inF = x [bs, N, 64] fp32, row r -> (n=r>>3, b=r&7)
// layout==1: input inH = g_x16 [N*8, 64] fp16, row r contiguous
#define A_PAD 68
__global__ void __launch_bounds__(256) gemm_kernel(
        const float* __restrict__ inF, const __half* __restrict__ inH,
        const float* __restrict__ W, __half* __restrict__ out16, int layout) {
    __shared__ float sA[64][A_PAD];
    __shared__ float sW[64][64];
    int tid = threadIdx.x;
    int rbase = blockIdx.x * 64;
    for (int i = tid; i < 1024; i += 256) {
        int k = i >> 4, f4 = i & 15;
        ((float4*)&sW[k][0])[f4] = ((const float4*)W)[i];
    }
    for (int i = tid; i < 1024; i += 256) {
        int rr = i >> 4, c4 = i & 15;
        int grow = rbase + rr;
        float4 v = make_float4(0.f, 0.f, 0.f, 0.f);
        if (grow < NROWS) {
            if (layout == 0) {
                int nn = grow >> 3, bb = grow & 7;
                v = ((const float4*)(inF + ((size_t)bb * N_GENES + nn) * 64))[c4];
            } else {
                Half4 r; r.u = ((const uint2*)inH)[(size_t)grow * 16 + c4];
                float2 a = __half22float2(r.h[0]);
                float2 b = __half22float2(r.h[1]);
                v = make_float4(a.x, a.y, b.x, b.y);
            }
        }
        ((float4*)&sA[rr][0])[c4] = v;
    }
    __syncthreads();
    int tx = tid & 15, ty = tid >> 4;
    float acc[4][4];
#pragma unroll
    for (int i = 0; i < 4; i++)
#pragma unroll
        for (int j = 0; j < 4; j++) acc[i][j] = 0.f;
#pragma unroll 4
    for (int k = 0; k < 64; k++) {
        float4 b = *(const float4*)&sW[k][tx * 4];
        float a0 = sA[ty * 4 + 0][k];
        float a1 = sA[ty * 4 + 1][k];
        float a2 = sA[ty * 4 + 2][k];
        float a3 = sA[ty * 4 + 3][k];
        acc[0][0] += a0 * b.x; acc[0][1] += a0 * b.y; acc[0][2] += a0 * b.z; acc[0][3] += a0 * b.w;
        acc[1][0] += a1 * b.x; acc[1][1] += a1 * b.y; acc[1][2] += a1 * b.z; acc[1][3] += a1 * b.w;
        acc[2][0] += a2 * b.x; acc[2][1] += a2 * b.y; acc[2][2] += a2 * b.z; acc[2][3] += a2 * b.w;
        acc[3][0] += a3 * b.x; acc[3][1] += a3 * b.y; acc[3][2] += a3 * b.z; acc[3][3] += a3 * b.w;
    }
#pragma unroll
    for (int i = 0; i < 4; i++) {
        int grow = rbase + ty * 4 + i;
        if (grow < NROWS) {
            Half4 pk;
            pk.h[0] = __floats2half2_rn(acc[i][0], acc[i][1]);
            pk.h[1] = __floats2half2_rn(acc[i][2], acc[i][3]);
            ((uint2*)out16)[(size_t)grow * 16 + tx] = pk.u;
        }
    }
}

// ------------------- GCN aggregate + fc-dot (uint4 gather, 2-edge groups) ----
// node row = 64 uint4 lanes; block = 128 thr = 2 groups x 64 lanes.
// lane covers halfs 8*lane..+7 -> batch = lane>>3, dims d0=8*(lane&7)..+7
__global__ void __launch_bounds__(128) agg_kernel(
        const __half* __restrict__ h16, const float* __restrict__ bias,
        __half* __restrict__ xout16, const float* __restrict__ fcW,
        int fc_off, int accum) {
    __shared__ int   sSrc[128];
    __shared__ float sNrm[128];
    __shared__ float sComb[64 * 8];           // group-1 partials

    int n = blockIdx.x;
    int t = threadIdx.x;
    int g = t >> 6;                            // edge group 0/1
    int lane = t & 63;
    const uint4* __restrict__ h4 = (const uint4*)h16;   // row = 64 uint4

    float4 aLo = make_float4(0.f, 0.f, 0.f, 0.f);
    float4 aHi = make_float4(0.f, 0.f, 0.f, 0.f);
    float4 bLo = make_float4(0.f, 0.f, 0.f, 0.f);
    float4 bHi = make_float4(0.f, 0.f, 0.f, 0.f);

    // self-loop term (group 0 only)
    if (g == 0) {
        float w0 = g_dinv[n]; w0 *= w0;
        Half8 r; r.u = h4[(size_t)n * 64 + lane];
        float2 c0 = __half22float2(r.h[0]);
        float2 c1 = __half22float2(r.h[1]);
        float2 c2 = __half22float2(r.h[2]);
        float2 c3 = __half22float2(r.h[3]);
        aLo = make_float4(w0 * c0.x, w0 * c0.y, w0 * c1.x, w0 * c1.y);
        aHi = make_float4(w0 * c2.x, w0 * c2.y, w0 * c3.x, w0 * c3.y);
    }

    int e0 = g_rowptr[n], e1 = g_rowptr[n + 1];
    for (int cs = e0; cs < e1; cs += 128) {
        int idx = cs + t;
        if (idx < e1) { sSrc[t] = g_csr_src[idx]; sNrm[t] = g_csr_norm[idx]; }
        __syncthreads();
        int m = e1 - cs; if (m > 128) m = 128;
        int jb = 0;
        for (; jb + 8 <= m; jb += 8) {
            int j0 = jb + g, j1 = jb + 2 + g, j2 = jb + 4 + g, j3 = jb + 6 + g;
            float u0 = sNrm[j0], u1 = sNrm[j1], u2 = sNrm[j2], u3 = sNrm[j3];
            Half8 r0, r1, r2, r3;
            r0.u = h4[(size_t)sSrc[j0] * 64 + lane];
            r1.u = h4[(size_t)sSrc[j1] * 64 + lane];
            r2.u = h4[(size_t)sSrc[j2] * 64 + lane];
            r3.u = h4[(size_t)sSrc[j3] * 64 + lane];
            float2 c0, c1, c2, c3;
            c0 = __half22float2(r0.h[0]); c1 = __half22float2(r0.h[1]);
            c2 = __half22float2(r0.h[2]); c3 = __half22float2(r0.h[3]);
            aLo.x += u0 * c0.x; aLo.y += u0 * c0.y; aLo.z += u0 * c1.x; aLo.w += u0 * c1.y;
            aHi.x += u0 * c2.x; aHi.y += u0 * c2.y; aHi.z += u0 * c3.x; aHi.w += u0 * c3.y;
            c0 = __half22float2(r1.h[0]); c1 = __half22float2(r1.h[1]);
            c2 = __half22float2(r1.h[2]); c3 = __half22float2(r1.h[3]);
            bLo.x += u1 * c0.x; bLo.y += u1 * c0.y; bLo.z += u1 * c1.x; bLo.w += u1 * c1.y;
            bHi.x += u1 * c2.x; bHi.y += u1 * c2.y; bHi.z += u1 * c3.x; bHi.w += u1 * c3.y;
            c0 = __half22float2(r2.h[0]); c1 = __half22float2(r2.h[1]);
            c2 = __half22float2(r2.h[2]); c3 = __half22float2(r2.h[3]);
            aLo.x += u2 * c0.x; aLo.y += u2 * c0.y; aLo.z += u2 * c1.x; aLo.w += u2 * c1.y;
            aHi.x += u2 * c2.x; aHi.y += u2 * c2.y; aHi.z += u2 * c3.x; aHi.w += u2 * c3.y;
            c0 = __half22float2(r3.h[0]); c1 = __half22float2(r3.h[1]);
            c2 = __half22float2(r3.h[2]); c3 = __half22float2(r3.h[3]);
            bLo.x += u3 * c0.x; bLo.y += u3 * c0.y; bLo.z += u3 * c1.x; bLo.w += u3 * c1.y;
            bHi.x += u3 * c2.x; bHi.y += u3 * c2.y; bHi.z += u3 * c3.x; bHi.w += u3 * c3.y;
        }
        for (int j = jb + g; j < m; j += 2) {
            float u = sNrm[j];
            Half8 r; r.u = h4[(size_t)sSrc[j] * 64 + lane];
            float2 c0 = __half22float2(r.h[0]);
            float2 c1 = __half22float2(r.h[1]);
            float2 c2 = __half22float2(r.h[2]);
            float2 c3 = __half22float2(r.h[3]);
            aLo.x += u * c0.x; aLo.y += u * c0.y; aLo.z += u * c1.x; aLo.w += u * c1.y;
            aHi.x += u * c2.x; aHi.y += u * c2.y; aHi.z += u * c3.x; aHi.w += u * c3.y;
        }
        __syncthreads();
    }
    aLo.x += bLo.x; aLo.y += bLo.y; aLo.z += bLo.z; aLo.w += bLo.w;
    aHi.x += bHi.x; aHi.y += bHi.y; aHi.z += bHi.z; aHi.w += bHi.w;

    // combine group 1 into group 0 via smem
    if (g == 1) {
        float4* c4p = (float4*)(sComb + lane * 8);
        c4p[0] = aLo; c4p[1] = aHi;
    }
    __syncthreads();
    if (g == 0) {
        const float4* c4p = (const float4*)(sComb + lane * 8);
        float4 pLo = c4p[0], pHi = c4p[1];
        aLo.x += pLo.x; aLo.y += pLo.y; aLo.z += pLo.z; aLo.w += pLo.w;
        aHi.x += pHi.x; aHi.y += pHi.y; aHi.z += pHi.z; aHi.w += pHi.w;

        int d0 = 8 * (lane & 7);
        float4 bb0 = ((const float4*)bias)[2 * (lane & 7)];
        float4 bb1 = ((const float4*)bias)[2 * (lane & 7) + 1];
        aLo.x = fmaxf(aLo.x + bb0.x, 0.f);
        aLo.y = fmaxf(aLo.y + bb0.y, 0.f);
        aLo.z = fmaxf(aLo.z + bb0.z, 0.f);
        aLo.w = fmaxf(aLo.w + bb0.w, 0.f);
        aHi.x = fmaxf(aHi.x + bb1.x, 0.f);
        aHi.y = fmaxf(aHi.y + bb1.y, 0.f);
        aHi.z = fmaxf(aHi.z + bb1.z, 0.f);
        aHi.w = fmaxf(aHi.w + bb1.w, 0.f);

        // fc-dot over this thread's 8 dims
        float sp = aLo.x * fcW[3 * d0 + fc_off]
                 + aLo.y * fcW[3 * (d0 + 1) + fc_off]
                 + aLo.z * fcW[3 * (d0 + 2) + fc_off]
                 + aLo.w * fcW[3 * (d0 + 3) + fc_off]
                 + aHi.x * fcW[3 * (d0 + 4) + fc_off]
                 + aHi.y * fcW[3 * (d0 + 5) + fc_off]
                 + aHi.z * fcW[3 * (d0 + 6) + fc_off]
                 + aHi.w * fcW[3 * (d0 + 7) + fc_off];
#pragma unroll
        for (int off = 4; off; off >>= 1) sp += __shfl_xor_sync(0xffffffffu, sp, off);
        if ((lane & 7) == 0) {
            size_t idx = (size_t)n * 8 + (lane >> 3);
            g_s[idx] = accum ? (g_s[idx] + sp) : sp;
        }

        if (xout16) {
            Half8 pk;
            pk.h[0] = __floats2half2_rn(aLo.x, aLo.y);
            pk.h[1] = __floats2half2_rn(aLo.z, aLo.w);
            pk.h[2] = __floats2half2_rn(aHi.x, aHi.y);
            pk.h[3] = __floats2half2_rn(aHi.z, aHi.w);
            ((uint4*)xout16)[(size_t)n * 64 + lane] = pk.u;
        }
    }
}

// ------------------- pathway pooled mean via CSR (deterministic, double) ----
__global__ void __launch_bounds__(256) pool_kernel(const float* __restrict__ fcb) {
    __shared__ double sh[256];
    int c = blockIdx.x;
    int tid = threadIdx.x;
    int b = tid & 7;
    int i = tid >> 3;
    int e0 = g_rowptr2[c], e1 = g_rowptr2[c + 1];
    double acc = 0.0;
    for (int e = e0 + i; e < e1; e += 32) {
        int r = g_csr2_row[e];
        acc += (double)g_s[(size_t)r * 8 + b];
    }
    sh[tid] = acc;
    __syncthreads();
    for (int off = 128; off >= 8; off >>= 1) {
        if (tid < off) sh[tid] += sh[tid + off];
        __syncthreads();
    }
    if (tid < 8) {
        double cnt = (double)(e1 - e0);
        if (cnt < 1.0) cnt = 1.0;
        g_pool[c * 8 + tid] = (float)(sh[tid] / cnt + (double)fcb[0]);
    }
}

// ------------------- MLP head ------------------------------------------------
__global__ void __launch_bounds__(128) mlp1_kernel(const float* __restrict__ l1W) {
    int b = blockIdx.x & 7;
    int chunk = blockIdx.x >> 3;
    int j = threadIdx.x;
    int c0 = chunk * 125, c1 = c0 + 125;
    float acc = 0.f;
    for (int c = c0; c < c1; c++)
        acc += g_pool[c * 8 + b] * l1W[c * HFC + j];
    g_part[((size_t)chunk * 8 + b) * HFC + j] = acc;
}

__global__ void __launch_bounds__(128) mlp2_kernel(
        const float* __restrict__ l1b, const float* __restrict__ l2W,
        const float* __restrict__ l2b, float* __restrict__ out) {
    __shared__ double sz0[128], sz1[128];
    int b = blockIdx.x, j = threadIdx.x;
    double hv = (double)l1b[j];
#pragma unroll
    for (int k = 0; k < 8; k++) hv += (double)g_part[((size_t)k * 8 + b) * HFC + j];
    if (hv < 0.0) hv = 0.0;
    sz0[j] = hv * (double)l2W[j * 2];
    sz1[j] = hv * (double)l2W[j * 2 + 1];
    __syncthreads();
    for (int off = 64; off; off >>= 1) {
        if (j < off) { sz0[j] += sz0[j + off]; sz1[j] += sz1[j + off]; }
        __syncthreads();
    }
    if (j == 0) {
        double z0 = sz0[0] + (double)l2b[0];
        double z1 = sz1[0] + (double)l2b[1];
        double m = z0 > z1 ? z0 : z1;
        double lse = m + log(exp(z0 - m) + exp(z1 - m));
        out[b * 2]     = (float)(z0 - lse);
        out[b * 2 + 1] = (float)(z1 - lse);
    }
}

// ------------------- launch --------------------------------------------------
extern "C" void kernel_launch(void* const* d_in, const int* in_sizes, int n_in,
                              void* d_out, int out_size) {
    const float* x    = (const float*)d_in[0];
    const int*   ei   = (const int*)  d_in[2];
    const int*   prow = (const int*)  d_in[3];
    const int*   pcol = (const int*)  d_in[4];
    const float* W1   = (const float*)d_in[5];
    const float* b1   = (const float*)d_in[6];
    const float* W2   = (const float*)d_in[7];
    const float* b2   = (const float*)d_in[8];
    const float* W3   = (const float*)d_in[9];
    const float* b3   = (const float*)d_in[10];
    const float* fcW  = (const float*)d_in[11];
    const float* fcb  = (const float*)d_in[12];
    const float* l1W  = (const float*)d_in[13];
    const float* l1b  = (const float*)d_in[14];
    const float* l2W  = (const float*)d_in[15];
    const float* l2b  = (const float*)d_in[16];
    float* out = (float*)d_out;

    int E = in_sizes[2] / 2;
    int P = in_sizes[3];
    int EP = E > P ? E : P;

    int gemm_blocks = (NROWS + 63) / 64;                      // 1892

    // launch order (ncu captures idx 3 = gemm1):
    zero_kernel<<<(N_GENES + 255) / 256, 256>>>();                              // 0
    degrees_kernel<<<(EP + 255) / 256, 256>>>(ei, E, pcol, P);                  // 1
    scans_kernel<<<2, 1024>>>();                                                // 2
    gemm_kernel<<<gemm_blocks, 256>>>(x, (const __half*)0, W1, g_h16, 0);       // 3 <- profiled
    fills_kernel<<<(EP + 255) / 256, 256>>>(ei, E, prow, pcol, P);              // 4
    agg_kernel<<<N_GENES, 128>>>(g_h16, b1, g_x16, fcW, 0, 0);                  // 5
    gemm_kernel<<<gemm_blocks, 256>>>((const float*)0, g_x16, W2, g_h16, 1);    // 6
    agg_kernel<<<N_GENES, 128>>>(g_h16, b2, g_x16, fcW, 1, 1);                  // 7
    gemm_kernel<<<gemm_blocks, 256>>>((const float*)0, g_x16, W3, g_h16, 1);    // 8
    agg_kernel<<<N_GENES, 128>>>(g_h16, b3, (__half*)0, fcW, 2, 1);             // 9
    pool_kernel<<<NCMT, 256>>>(fcb);                                            // 10
    mlp1_kernel<<<64, HFC>>>(l1W);                                              // 11
    mlp2_kernel<<<BS, HFC>>>(l1b, l2W, l2b, out);                               // 12
}

// round 16
// speedup vs baseline: 3.3364x; 1.0672x over previous
#include <cuda_runtime.h>
#include <cuda_fp16.h>
#include <math.h>

#define N_GENES 15135
#define BS 8
#define HID 64
#define NCMT 1000
#define HFC 128
#define NROWS (N_GENES * BS)       // 121080
#define FPN (BS * HID)             // 512 halfs per node
#define E_MAX 262144
#define P_MAX 131072

// ------------------- scratch (static device globals; no runtime alloc) -----
__device__ __half g_h16[(size_t)N_GENES * FPN];   // 15.5 MB (gathered operand)
__device__ float g_dinv[N_GENES];
__device__ int   g_cnt [N_GENES];
__device__ int   g_fill[N_GENES];
__device__ int   g_rowptr[N_GENES + 1];
__device__ int   g_csr_src [E_MAX];
__device__ float g_csr_norm[E_MAX];
__device__ int   g_cnt2 [NCMT];
__device__ int   g_fill2[NCMT];
__device__ int   g_rowptr2[NCMT + 1];
__device__ int   g_csr2_row[P_MAX];
__device__ float g_s[(size_t)NROWS];      // s[n*8+b], accumulated across 3 layers
__device__ float g_pool[NCMT * BS];       // pooled mean + fcb, [c*8+b]
__device__ float g_part[8 * BS * HFC];    // mlp1 partials [chunk][b][j]

union Half4 { uint2 u; __half2 h[2]; };
union Half8 { uint4 u; __half2 h[4]; };

// ------------------- setup: zero, parallel degrees, scans, fills ------------
__global__ void zero_kernel() {
    int i = blockIdx.x * blockDim.x + threadIdx.x;
    if (i < N_GENES) { g_cnt[i] = 0; g_fill[i] = 0; }
    if (i < NCMT)    { g_cnt2[i] = 0; g_fill2[i] = 0; }
}

__global__ void degrees_kernel(const int* __restrict__ ei, int E,
                               const int* __restrict__ pcol, int P) {
    int i = blockIdx.x * blockDim.x + threadIdx.x;
    if (i < E) atomicAdd(&g_cnt[ei[E + i]], 1);
    if (i < P) atomicAdd(&g_cnt2[pcol[i]], 1);
}

__global__ void scans_kernel() {
    __shared__ int sh[1024];
    int tid = threadIdx.x;
    if (blockIdx.x == 0) {
        int carry = 0;
        for (int base = 0; base < N_GENES; base += 1024) {
            int i = base + tid;
            int v = (i < N_GENES) ? g_cnt[i] : 0;
            if (i < N_GENES) g_dinv[i] = 1.0f / sqrtf((float)v + 1.0f);
            sh[tid] = v;
            __syncthreads();
            for (int off = 1; off < 1024; off <<= 1) {
                int t = (tid >= off) ? sh[tid - off] : 0;
                __syncthreads();
                sh[tid] += t;
                __syncthreads();
            }
            if (i < N_GENES) g_rowptr[i] = carry + sh[tid] - v;  // exclusive
            carry += sh[1023];
            __syncthreads();
        }
        if (tid == 0) g_rowptr[N_GENES] = carry;
    } else {
        int v = (tid < NCMT) ? g_cnt2[tid] : 0;
        sh[tid] = v;
        __syncthreads();
        for (int off = 1; off < 1024; off <<= 1) {
            int t = (tid >= off) ? sh[tid - off] : 0;
            __syncthreads();
            sh[tid] += t;
            __syncthreads();
        }
        if (tid < NCMT) g_rowptr2[tid] = sh[tid] - v;
        if (tid == NCMT - 1) g_rowptr2[NCMT] = sh[tid];
    }
}

__global__ void fills_kernel(const int* __restrict__ ei, int E,
                             const int* __restrict__ prow,
                             const int* __restrict__ pcol, int P) {
    int i = blockIdx.x * blockDim.x + threadIdx.x;
    if (i < E) {
        int src = ei[i];
        int dst = ei[E + i];
        int pos = g_rowptr[dst] + atomicAdd(&g_fill[dst], 1);
        g_csr_src[pos] = src;
        g_csr_norm[pos] = g_dinv[src] * g_dinv[dst];
    }
    if (i < P) {
        int c = pcol[i];
        int pos = g_rowptr2[c] + atomicAdd(&g_fill2[c], 1);
        g_csr2_row[pos] = prow[i];
    }
}

// ------------------- GEMM1 (layer 1 only; 64x64 register tile) ---------------
// h16[r*64+f] = (half) sum_k x_row(r)[k] * W[k*64+f];  row r -> (n=r>>3, b=r&7)
#define A_PAD 68
__global__ void __launch_bounds__(256) gemm_kernel(
        const float* __restrict__ inF, const float* __restrict__ W,
        __half* __restrict__ out16) {
    __shared__ float sA[64][A_PAD];
    __shared__ float sW[64][64];
    int tid = threadIdx.x;
    int rbase = blockIdx.x * 64;
    for (int i = tid; i < 1024; i += 256) {
        int k = i >> 4, f4 = i & 15;
        ((float4*)&sW[k][0])[f4] = ((const float4*)W)[i];
    }
    for (int i = tid; i < 1024; i += 256) {
        int rr = i >> 4, c4 = i & 15;
        int grow = rbase + rr;
        float4 v = make_float4(0.f, 0.f, 0.f, 0.f);
        if (grow < NROWS) {
            int nn = grow >> 3, bb = grow & 7;
            v = ((const float4*)(inF + ((size_t)bb * N_GENES + nn) * 64))[c4];
        }
        ((float4*)&sA[rr][0])[c4] = v;
    }
    __syncthreads();
    int tx = tid & 15, ty = tid >> 4;
    float acc[4][4];
#pragma unroll
    for (int i = 0; i < 4; i++)
#pragma unroll
        for (int j = 0; j < 4; j++) acc[i][j] = 0.f;
#pragma unroll 4
    for (int k = 0; k < 64; k++) {
        float4 b = *(const float4*)&sW[k][tx * 4];
        float a0 = sA[ty * 4 + 0][k];
        float a1 = sA[ty * 4 + 1][k];
        float a2 = sA[ty * 4 + 2][k];
        float a3 = sA[ty * 4 + 3][k];
        acc[0][0] += a0 * b.x; acc[0][1] += a0 * b.y; acc[0][2] += a0 * b.z; acc[0][3] += a0 * b.w;
        acc[1][0] += a1 * b.x; acc[1][1] += a1 * b.y; acc[1][2] += a1 * b.z; acc[1][3] += a1 * b.w;
        acc[2][0] += a2 * b.x; acc[2][1] += a2 * b.y; acc[2][2] += a2 * b.z; acc[2][3] += a2 * b.w;
        acc[3][0] += a3 * b.x; acc[3][1] += a3 * b.y; acc[3][2] += a3 * b.z; acc[3][3] += a3 * b.w;
    }
#pragma unroll
    for (int i = 0; i < 4; i++) {
        int grow = rbase + ty * 4 + i;
        if (grow < NROWS) {
            Half4 pk;
            pk.h[0] = __floats2half2_rn(acc[i][0], acc[i][1]);
            pk.h[1] = __floats2half2_rn(acc[i][2], acc[i][3]);
            ((uint2*)out16)[(size_t)grow * 16 + tx] = pk.u;
        }
    }
}

// ------------------- fused agg + fc-dot + (optional) next-layer GEMM ---------
// x = relu(sum_e w*h16[src] + dinv^2*h16[n] + bias)   (fp32 regs)
// s[n,b] (+)= x . fcW_col
// if Wn: h16out[n] = (half)(x @ Wn)   — W staged in smem once per block
__global__ void __launch_bounds__(128) agg_kernel(
        const __half* __restrict__ h16, const float* __restrict__ bias,
        const float* __restrict__ Wn, __half* __restrict__ hout16,
        const float* __restrict__ fcW, int fc_off, int accum) {
    __shared__ float sW[4096];                // 16 KB next-layer W
    __shared__ float sX[512];                 // x tile [b][64] fp32
    __shared__ int   sSrc[128];
    __shared__ float sNrm[128];

    int n = blockIdx.x;
    int t = threadIdx.x;
    int g = t >> 6;                            // edge group 0/1
    int lane = t & 63;
    const uint4* __restrict__ h4 = (const uint4*)h16;   // row = 64 uint4

    // stage next-layer W while the gather runs
    if (Wn) {
        for (int i = t; i < 1024; i += 128)
            ((float4*)sW)[i] = __ldg(((const float4*)Wn) + i);
    }

    float4 aLo = make_float4(0.f, 0.f, 0.f, 0.f);
    float4 aHi = make_float4(0.f, 0.f, 0.f, 0.f);
    float4 bLo = make_float4(0.f, 0.f, 0.f, 0.f);
    float4 bHi = make_float4(0.f, 0.f, 0.f, 0.f);

    if (g == 0) {   // self-loop term
        float w0 = g_dinv[n]; w0 *= w0;
        Half8 r; r.u = h4[(size_t)n * 64 + lane];
        float2 c0 = __half22float2(r.h[0]);
        float2 c1 = __half22float2(r.h[1]);
        float2 c2 = __half22float2(r.h[2]);
        float2 c3 = __half22float2(r.h[3]);
        aLo = make_float4(w0 * c0.x, w0 * c0.y, w0 * c1.x, w0 * c1.y);
        aHi = make_float4(w0 * c2.x, w0 * c2.y, w0 * c3.x, w0 * c3.y);
    }

    int e0 = g_rowptr[n], e1 = g_rowptr[n + 1];
    for (int cs = e0; cs < e1; cs += 128) {
        int idx = cs + t;
        if (idx < e1) { sSrc[t] = g_csr_src[idx]; sNrm[t] = g_csr_norm[idx]; }
        __syncthreads();
        int m = e1 - cs; if (m > 128) m = 128;
        int jb = 0;
        for (; jb + 8 <= m; jb += 8) {
            int j0 = jb + g, j1 = jb + 2 + g, j2 = jb + 4 + g, j3 = jb + 6 + g;
            float u0 = sNrm[j0], u1 = sNrm[j1], u2 = sNrm[j2], u3 = sNrm[j3];
            Half8 r0, r1, r2, r3;
            r0.u = h4[(size_t)sSrc[j0] * 64 + lane];
            r1.u = h4[(size_t)sSrc[j1] * 64 + lane];
            r2.u = h4[(size_t)sSrc[j2] * 64 + lane];
            r3.u = h4[(size_t)sSrc[j3] * 64 + lane];
            float2 c0, c1, c2, c3;
            c0 = __half22float2(r0.h[0]); c1 = __half22float2(r0.h[1]);
            c2 = __half22float2(r0.h[2]); c3 = __half22float2(r0.h[3]);
            aLo.x += u0 * c0.x; aLo.y += u0 * c0.y; aLo.z += u0 * c1.x; aLo.w += u0 * c1.y;
            aHi.x += u0 * c2.x; aHi.y += u0 * c2.y; aHi.z += u0 * c3.x; aHi.w += u0 * c3.y;
            c0 = __half22float2(r1.h[0]); c1 = __half22float2(r1.h[1]);
            c2 = __half22float2(r1.h[2]); c3 = __half22float2(r1.h[3]);
            bLo.x += u1 * c0.x; bLo.y += u1 * c0.y; bLo.z += u1 * c1.x; bLo.w += u1 * c1.y;
            bHi.x += u1 * c2.x; bHi.y += u1 * c2.y; bHi.z += u1 * c3.x; bHi.w += u1 * c3.y;
            c0 = __half22float2(r2.h[0]); c1 = __half22float2(r2.h[1]);
            c2 = __half22float2(r2.h[2]); c3 = __half22float2(r2.h[3]);
            aLo.x += u2 * c0.x; aLo.y += u2 * c0.y; aLo.z += u2 * c1.x; aLo.w += u2 * c1.y;
            aHi.x += u2 * c2.x; aHi.y += u2 * c2.y; aHi.z += u2 * c3.x; aHi.w += u2 * c3.y;
            c0 = __half22float2(r3.h[0]); c1 = __half22float2(r3.h[1]);
            c2 = __half22float2(r3.h[2]); c3 = __half22float2(r3.h[3]);
            bLo.x += u3 * c0.x; bLo.y += u3 * c0.y; bLo.z += u3 * c1.x; bLo.w += u3 * c1.y;
            bHi.x += u3 * c2.x; bHi.y += u3 * c2.y; bHi.z += u3 * c3.x; bHi.w += u3 * c3.y;
        }
        for (int j = jb + g; j < m; j += 2) {
            float u = sNrm[j];
            Half8 r; r.u = h4[(size_t)sSrc[j] * 64 + lane];
            float2 c0 = __half22float2(r.h[0]);
            float2 c1 = __half22float2(r.h[1]);
            float2 c2 = __half22float2(r.h[2]);
            float2 c3 = __half22float2(r.h[3]);
            aLo.x += u * c0.x; aLo.y += u * c0.y; aLo.z += u * c1.x; aLo.w += u * c1.y;
            aHi.x += u * c2.x; aHi.y += u * c2.y; aHi.z += u * c3.x; aHi.w += u * c3.y;
        }
        __syncthreads();
    }
    aLo.x += bLo.x; aLo.y += bLo.y; aLo.z += bLo.z; aLo.w += bLo.w;
    aHi.x += bHi.x; aHi.y += bHi.y; aHi.z += bHi.z; aHi.w += bHi.w;

    // combine group 1 into group 0 via sX scratch (reused before x staging)
    if (g == 1) {
        float4* c4p = (float4*)(sX + lane * 8);
        c4p[0] = aLo; c4p[1] = aHi;
    }
    __syncthreads();
    if (g == 0) {
        const float4* c4p = (const float4*)(sX + lane * 8);
        float4 pLo = c4p[0], pHi = c4p[1];
        aLo.x += pLo.x; aLo.y += pLo.y; aLo.z += pLo.z; aLo.w += pLo.w;
        aHi.x += pHi.x; aHi.y += pHi.y; aHi.z += pHi.z; aHi.w += pHi.w;

        int d0 = 8 * (lane & 7);
        float4 bb0 = ((const float4*)bias)[2 * (lane & 7)];
        float4 bb1 = ((const float4*)bias)[2 * (lane & 7) + 1];
        aLo.x = fmaxf(aLo.x + bb0.x, 0.f);
        aLo.y = fmaxf(aLo.y + bb0.y, 0.f);
        aLo.z = fmaxf(aLo.z + bb0.z, 0.f);
        aLo.w = fmaxf(aLo.w + bb0.w, 0.f);
        aHi.x = fmaxf(aHi.x + bb1.x, 0.f);
        aHi.y = fmaxf(aHi.y + bb1.y, 0.f);
        aHi.z = fmaxf(aHi.z + bb1.z, 0.f);
        aHi.w = fmaxf(aHi.w + bb1.w, 0.f);

        // fc-dot over this thread's 8 dims (fp32 x)
        float sp = aLo.x * fcW[3 * d0 + fc_off]
                 + aLo.y * fcW[3 * (d0 + 1) + fc_off]
                 + aLo.z * fcW[3 * (d0 + 2) + fc_off]
                 + aLo.w * fcW[3 * (d0 + 3) + fc_off]
                 + aHi.x * fcW[3 * (d0 + 4) + fc_off]
                 + aHi.y * fcW[3 * (d0 + 5) + fc_off]
                 + aHi.z * fcW[3 * (d0 + 6) + fc_off]
                 + aHi.w * fcW[3 * (d0 + 7) + fc_off];
#pragma unroll
        for (int off = 4; off; off >>= 1) sp += __shfl_xor_sync(0xffffffffu, sp, off);
        if ((lane & 7) == 0) {
            size_t idx = (size_t)n * 8 + (lane >> 3);
            g_s[idx] = accum ? (g_s[idx] + sp) : sp;
        }
    }

    // epilogue GEMM: h16out[n][b][f] = sum_k x[b][k] * Wn[k][f]
    if (Wn) {
        __syncthreads();            // protect sX combine reads
        if (g == 0) {               // stage fp32 x: sX[b*64 + d0..d0+7]
            int b = lane >> 3, d0 = 8 * (lane & 7);
            float* xp = sX + b * 64 + d0;
            xp[0] = aLo.x; xp[1] = aLo.y; xp[2] = aLo.z; xp[3] = aLo.w;
            xp[4] = aHi.x; xp[5] = aHi.y; xp[6] = aHi.z; xp[7] = aHi.w;
        }
        __syncthreads();
        int b = t >> 4, q = t & 15;                // output halfs 4q..4q+3
        const float* xrow = sX + b * 64;
        float4 o = make_float4(0.f, 0.f, 0.f, 0.f);
#pragma unroll 8
        for (int k = 0; k < 64; k++) {
            float a = xrow[k];
            float4 w = ((const float4*)sW)[k * 16 + q];
            o.x += a * w.x; o.y += a * w.y; o.z += a * w.z; o.w += a * w.w;
        }
        Half4 pk;
        pk.h[0] = __floats2half2_rn(o.x, o.y);
        pk.h[1] = __floats2half2_rn(o.z, o.w);
        ((uint2*)hout16)[(size_t)n * 128 + b * 16 + q] = pk.u;
    }
}

// ------------------- pathway pooled mean via CSR (deterministic, double) ----
__global__ void __launch_bounds__(256) pool_kernel(const float* __restrict__ fcb) {
    __shared__ double sh[256];
    int c = blockIdx.x;
    int tid = threadIdx.x;
    int b = tid & 7;
    int i = tid >> 3;
    int e0 = g_rowptr2[c], e1 = g_rowptr2[c + 1];
    double acc = 0.0;
    for (int e = e0 + i; e < e1; e += 32) {
        int r = g_csr2_row[e];
        acc += (double)g_s[(size_t)r * 8 + b];
    }
    sh[tid] = acc;
    __syncthreads();
    for (int off = 128; off >= 8; off >>= 1) {
        if (tid < off) sh[tid] += sh[tid + off];
        __syncthreads();
    }
    if (tid < 8) {
        double cnt = (double)(e1 - e0);
        if (cnt < 1.0) cnt = 1.0;
        g_pool[c * 8 + tid] = (float)(sh[tid] / cnt + (double)fcb[0]);
    }
}

// ------------------- MLP head ------------------------------------------------
__global__ void __launch_bounds__(128) mlp1_kernel(const float* __restrict__ l1W) {
    int b = blockIdx.x & 7;
    int chunk = blockIdx.x >> 3;
    int j = threadIdx.x;
    int c0 = chunk * 125, c1 = c0 + 125;
    float acc = 0.f;
    for (int c = c0; c < c1; c++)
        acc += g_pool[c * 8 + b] * l1W[c * HFC + j];
    g_part[((size_t)chunk * 8 + b) * HFC + j] = acc;
}

__global__ void __launch_bounds__(128) mlp2_kernel(
        const float* __restrict__ l1b, const float* __restrict__ l2W,
        const float* __restrict__ l2b, float* __restrict__ out) {
    __shared__ double sz0[128], sz1[128];
    int b = blockIdx.x, j = threadIdx.x;
    double hv = (double)l1b[j];
#pragma unroll
    for (int k = 0; k < 8; k++) hv += (double)g_part[((size_t)k * 8 + b) * HFC + j];
    if (hv < 0.0) hv = 0.0;
    sz0[j] = hv * (double)l2W[j * 2];
    sz1[j] = hv * (double)l2W[j * 2 + 1];
    __syncthreads();
    for (int off = 64; off; off >>= 1) {
        if (j < off) { sz0[j] += sz0[j + off]; sz1[j] += sz1[j + off]; }
        __syncthreads();
    }
    if (j == 0) {
        double z0 = sz0[0] + (double)l2b[0];
        double z1 = sz1[0] + (double)l2b[1];
        double m = z0 > z1 ? z0 : z1;
        double lse = m + log(exp(z0 - m) + exp(z1 - m));
        out[b * 2]     = (float)(z0 - lse);
        out[b * 2 + 1] = (float)(z1 - lse);
    }
}

// ------------------- launch --------------------------------------------------
extern "C" void kernel_launch(void* const* d_in, const int* in_sizes, int n_in,
                              void* d_out, int out_size) {
    const float* x    = (const float*)d_in[0];
    const int*   ei   = (const int*)  d_in[2];
    const int*   prow = (const int*)  d_in[3];
    const int*   pcol = (const int*)  d_in[4];
    const float* W1   = (const float*)d_in[5];
    const float* b1   = (const float*)d_in[6];
    const float* W2   = (const float*)d_in[7];
    const float* b2   = (const float*)d_in[8];
    const float* W3   = (const float*)d_in[9];
    const float* b3   = (const float*)d_in[10];
    const float* fcW  = (const float*)d_in[11];
    const float* fcb  = (const float*)d_in[12];
    const float* l1W  = (const float*)d_in[13];
    const float* l1b  = (const float*)d_in[14];
    const float* l2W  = (const float*)d_in[15];
    const float* l2b  = (const float*)d_in[16];
    float* out = (float*)d_out;

    int E = in_sizes[2] / 2;
    int P = in_sizes[3];
    int EP = E > P ? E : P;

    int gemm_blocks = (NROWS + 63) / 64;                      // 1892

    // launch order (ncu captures idx 3 = gemm1):
    zero_kernel<<<(N_GENES + 255) / 256, 256>>>();                              // 0
    degrees_kernel<<<(EP + 255) / 256, 256>>>(ei, E, pcol, P);                  // 1
    scans_kernel<<<2, 1024>>>();                                                // 2
    gemm_kernel<<<gemm_blocks, 256>>>(x, W1, g_h16);                            // 3 <- profiled
    fills_kernel<<<(EP + 255) / 256, 256>>>(ei, E, prow, pcol, P);              // 4
    agg_kernel<<<N_GENES, 128>>>(g_h16, b1, W2, g_h16, fcW, 0, 0);              // 5 (fused gemm2)
    agg_kernel<<<N_GENES, 128>>>(g_h16, b2, W3, g_h16, fcW, 1, 1);              // 6 (fused gemm3)
    agg_kernel<<<N_GENES, 128>>>(g_h16, b3, (const float*)0, (__half*)0,
                                 fcW, 2, 1);                                    // 7
    pool_kernel<<<NCMT, 256>>>(fcb);                                            // 8
    mlp1_kernel<<<64, HFC>>>(l1W);                                              // 9
    mlp2_kernel<<<BS, HFC>>>(l1b, l2W, l2b, out);                               // 10
}

// round 17
// speedup vs baseline: 3.3414x; 1.0015x over previous
#include <cuda_runtime.h>
#include <cuda_fp16.h>
#include <math.h>

#define N_GENES 15135
#define BS 8
#define HID 64
#define NCMT 1000
#define HFC 128
#define NROWS (N_GENES * BS)       // 121080
#define FPN (BS * HID)             // 512 halfs per node
#define E_MAX 262144
#define P_MAX 131072

// ------------------- scratch (static device globals; no runtime alloc) -----
__device__ __half g_hA[(size_t)N_GENES * FPN];    // 15.5 MB ping
__device__ __half g_hB[(size_t)N_GENES * FPN];    // 15.5 MB pong
__device__ float g_dinv[N_GENES];
__device__ int   g_cnt [N_GENES];
__device__ int   g_fill[N_GENES];
__device__ int   g_rowptr[N_GENES + 1];
__device__ int   g_csr_src [E_MAX];
__device__ float g_csr_norm[E_MAX];
__device__ int   g_cnt2 [NCMT];
__device__ int   g_fill2[NCMT];
__device__ int   g_rowptr2[NCMT + 1];
__device__ int   g_csr2_row[P_MAX];
__device__ float g_s[(size_t)NROWS];      // s[n*8+b], accumulated across 3 layers
__device__ float g_pool[NCMT * BS];       // pooled mean + fcb, [c*8+b]
__device__ float g_part[8 * BS * HFC];    // mlp1 partials [chunk][b][j]

union Half4 { uint2 u; __half2 h[2]; };
union Half8 { uint4 u; __half2 h[4]; };

// ------------------- setup: zero, parallel degrees, scans, fills ------------
__global__ void zero_kernel() {
    int i = blockIdx.x * blockDim.x + threadIdx.x;
    if (i < N_GENES) { g_cnt[i] = 0; g_fill[i] = 0; }
    if (i < NCMT)    { g_cnt2[i] = 0; g_fill2[i] = 0; }
}

__global__ void degrees_kernel(const int* __restrict__ ei, int E,
                               const int* __restrict__ pcol, int P) {
    int i = blockIdx.x * blockDim.x + threadIdx.x;
    if (i < E) atomicAdd(&g_cnt[ei[E + i]], 1);
    if (i < P) atomicAdd(&g_cnt2[pcol[i]], 1);
}

__global__ void scans_kernel() {
    __shared__ int sh[1024];
    int tid = threadIdx.x;
    if (blockIdx.x == 0) {
        int carry = 0;
        for (int base = 0; base < N_GENES; base += 1024) {
            int i = base + tid;
            int v = (i < N_GENES) ? g_cnt[i] : 0;
            if (i < N_GENES) g_dinv[i] = 1.0f / sqrtf((float)v + 1.0f);
            sh[tid] = v;
            __syncthreads();
            for (int off = 1; off < 1024; off <<= 1) {
                int t = (tid >= off) ? sh[tid - off] : 0;
                __syncthreads();
                sh[tid] += t;
                __syncthreads();
            }
            if (i < N_GENES) g_rowptr[i] = carry + sh[tid] - v;  // exclusive
            carry += sh[1023];
            __syncthreads();
        }
        if (tid == 0) g_rowptr[N_GENES] = carry;
    } else {
        int v = (tid < NCMT) ? g_cnt2[tid] : 0;
        sh[tid] = v;
        __syncthreads();
        for (int off = 1; off < 1024; off <<= 1) {
            int t = (tid >= off) ? sh[tid - off] : 0;
            __syncthreads();
            sh[tid] += t;
            __syncthreads();
        }
        if (tid < NCMT) g_rowptr2[tid] = sh[tid] - v;
        if (tid == NCMT - 1) g_rowptr2[NCMT] = sh[tid];
    }
}

__global__ void fills_kernel(const int* __restrict__ ei, int E,
                             const int* __restrict__ prow,
                             const int* __restrict__ pcol, int P) {
    int i = blockIdx.x * blockDim.x + threadIdx.x;
    if (i < E) {
        int src = ei[i];
        int dst = ei[E + i];
        int pos = g_rowptr[dst] + atomicAdd(&g_fill[dst], 1);
        g_csr_src[pos] = src;
        g_csr_norm[pos] = g_dinv[src] * g_dinv[dst];
    }
    if (i < P) {
        int c = pcol[i];
        int pos = g_rowptr2[c] + atomicAdd(&g_fill2[c], 1);
        g_csr2_row[pos] = prow[i];
    }
}

// ------------------- GEMM1 (layer 1 only; 64x64 register tile) ---------------
// h16[r*64+f] = (half) sum_k x_row(r)[k] * W[k*64+f];  row r -> (n=r>>3, b=r&7)
#define A_PAD 68
__global__ void __launch_bounds__(256) gemm_kernel(
        const float* __restrict__ inF, const float* __restrict__ W,
        __half* __restrict__ out16) {
    __shared__ float sA[64][A_PAD];
    __shared__ float sW[64][64];
    int tid = threadIdx.x;
    int rbase = blockIdx.x * 64;
    for (int i = tid; i < 1024; i += 256) {
        int k = i >> 4, f4 = i & 15;
        ((float4*)&sW[k][0])[f4] = ((const float4*)W)[i];
    }
    for (int i = tid; i < 1024; i += 256) {
        int rr = i >> 4, c4 = i & 15;
        int grow = rbase + rr;
        float4 v = make_float4(0.f, 0.f, 0.f, 0.f);
        if (grow < NROWS) {
            int nn = grow >> 3, bb = grow & 7;
            v = ((const float4*)(inF + ((size_t)bb * N_GENES + nn) * 64))[c4];
        }
        ((float4*)&sA[rr][0])[c4] = v;
    }
    __syncthreads();
    int tx = tid & 15, ty = tid >> 4;
    float acc[4][4];
#pragma unroll
    for (int i = 0; i < 4; i++)
#pragma unroll
        for (int j = 0; j < 4; j++) acc[i][j] = 0.f;
#pragma unroll 4
    for (int k = 0; k < 64; k++) {
        float4 b = *(const float4*)&sW[k][tx * 4];
        float a0 = sA[ty * 4 + 0][k];
        float a1 = sA[ty * 4 + 1][k];
        float a2 = sA[ty * 4 + 2][k];
        float a3 = sA[ty * 4 + 3][k];
        acc[0][0] += a0 * b.x; acc[0][1] += a0 * b.y; acc[0][2] += a0 * b.z; acc[0][3] += a0 * b.w;
        acc[1][0] += a1 * b.x; acc[1][1] += a1 * b.y; acc[1][2] += a1 * b.z; acc[1][3] += a1 * b.w;
        acc[2][0] += a2 * b.x; acc[2][1] += a2 * b.y; acc[2][2] += a2 * b.z; acc[2][3] += a2 * b.w;
        acc[3][0] += a3 * b.x; acc[3][1] += a3 * b.y; acc[3][2] += a3 * b.z; acc[3][3] += a3 * b.w;
    }
#pragma unroll
    for (int i = 0; i < 4; i++) {
        int grow = rbase + ty * 4 + i;
        if (grow < NROWS) {
            Half4 pk;
            pk.h[0] = __floats2half2_rn(acc[i][0], acc[i][1]);
            pk.h[1] = __floats2half2_rn(acc[i][2], acc[i][3]);
            ((uint2*)out16)[(size_t)grow * 16 + tx] = pk.u;
        }
    }
}

// ------------------- fused agg + fc-dot + (optional) next-layer GEMM ---------
// x = relu(sum_e w*h16[src] + dinv^2*h16[n] + bias)   (fp32 regs)
// s[n,b] (+)= x . fcW_col
// if Wn: hout16[n] = (half)(x @ Wn)  — hout16 is a DIFFERENT buffer (no race)
__global__ void __launch_bounds__(128) agg_kernel(
        const __half* __restrict__ h16, const float* __restrict__ bias,
        const float* __restrict__ Wn, __half* __restrict__ hout16,
        const float* __restrict__ fcW, int fc_off, int accum) {
    __shared__ float sW[4096];                // 16 KB next-layer W
    __shared__ float sComb[512];              // group-1 partials
    __shared__ float sX[512];                 // x tile [b][64] fp32
    __shared__ int   sSrc[128];
    __shared__ float sNrm[128];

    int n = blockIdx.x;
    int t = threadIdx.x;
    int g = t >> 6;                            // edge group 0/1
    int lane = t & 63;
    const uint4* __restrict__ h4 = (const uint4*)h16;   // row = 64 uint4

    // stage next-layer W while the gather runs
    if (Wn) {
        for (int i = t; i < 1024; i += 128)
            ((float4*)sW)[i] = __ldg(((const float4*)Wn) + i);
    }

    float4 aLo = make_float4(0.f, 0.f, 0.f, 0.f);
    float4 aHi = make_float4(0.f, 0.f, 0.f, 0.f);
    float4 bLo = make_float4(0.f, 0.f, 0.f, 0.f);
    float4 bHi = make_float4(0.f, 0.f, 0.f, 0.f);

    if (g == 0) {   // self-loop term
        float w0 = g_dinv[n]; w0 *= w0;
        Half8 r; r.u = h4[(size_t)n * 64 + lane];
        float2 c0 = __half22float2(r.h[0]);
        float2 c1 = __half22float2(r.h[1]);
        float2 c2 = __half22float2(r.h[2]);
        float2 c3 = __half22float2(r.h[3]);
        aLo = make_float4(w0 * c0.x, w0 * c0.y, w0 * c1.x, w0 * c1.y);
        aHi = make_float4(w0 * c2.x, w0 * c2.y, w0 * c3.x, w0 * c3.y);
    }

    int e0 = g_rowptr[n], e1 = g_rowptr[n + 1];
    for (int cs = e0; cs < e1; cs += 128) {
        int idx = cs + t;
        if (idx < e1) { sSrc[t] = g_csr_src[idx]; sNrm[t] = g_csr_norm[idx]; }
        __syncthreads();
        int m = e1 - cs; if (m > 128) m = 128;
        int jb = 0;
        for (; jb + 8 <= m; jb += 8) {
            int j0 = jb + g, j1 = jb + 2 + g, j2 = jb + 4 + g, j3 = jb + 6 + g;
            float u0 = sNrm[j0], u1 = sNrm[j1], u2 = sNrm[j2], u3 = sNrm[j3];
            Half8 r0, r1, r2, r3;
            r0.u = h4[(size_t)sSrc[j0] * 64 + lane];
            r1.u = h4[(size_t)sSrc[j1] * 64 + lane];
            r2.u = h4[(size_t)sSrc[j2] * 64 + lane];
            r3.u = h4[(size_t)sSrc[j3] * 64 + lane];
            float2 c0, c1, c2, c3;
            c0 = __half22float2(r0.h[0]); c1 = __half22float2(r0.h[1]);
            c2 = __half22float2(r0.h[2]); c3 = __half22float2(r0.h[3]);
            aLo.x += u0 * c0.x; aLo.y += u0 * c0.y; aLo.z += u0 * c1.x; aLo.w += u0 * c1.y;
            aHi.x += u0 * c2.x; aHi.y += u0 * c2.y; aHi.z += u0 * c3.x; aHi.w += u0 * c3.y;
            c0 = __half22float2(r1.h[0]); c1 = __half22float2(r1.h[1]);
            c2 = __half22float2(r1.h[2]); c3 = __half22float2(r1.h[3]);
            bLo.x += u1 * c0.x; bLo.y += u1 * c0.y; bLo.z += u1 * c1.x; bLo.w += u1 * c1.y;
            bHi.x += u1 * c2.x; bHi.y += u1 * c2.y; bHi.z += u1 * c3.x; bHi.w += u1 * c3.y;
            c0 = __half22float2(r2.h[0]); c1 = __half22float2(r2.h[1]);
            c2 = __half22float2(r2.h[2]); c3 = __half22float2(r2.h[3]);
            aLo.x += u2 * c0.x; aLo.y += u2 * c0.y; aLo.z += u2 * c1.x; aLo.w += u2 * c1.y;
            aHi.x += u2 * c2.x; aHi.y += u2 * c2.y; aHi.z += u2 * c3.x; aHi.w += u2 * c3.y;
            c0 = __half22float2(r3.h[0]); c1 = __half22float2(r3.h[1]);
            c2 = __half22float2(r3.h[2]); c3 = __half22float2(r3.h[3]);
            bLo.x += u3 * c0.x; bLo.y += u3 * c0.y; bLo.z += u3 * c1.x; bLo.w += u3 * c1.y;
            bHi.x += u3 * c2.x; bHi.y += u3 * c2.y; bHi.z += u3 * c3.x; bHi.w += u3 * c3.y;
        }
        for (int j = jb + g; j < m; j += 2) {
            float u = sNrm[j];
            Half8 r; r.u = h4[(size_t)sSrc[j] * 64 + lane];
            float2 c0 = __half22float2(r.h[0]);
            float2 c1 = __half22float2(r.h[1]);
            float2 c2 = __half22float2(r.h[2]);
            float2 c3 = __half22float2(r.h[3]);
            aLo.x += u * c0.x; aLo.y += u * c0.y; aLo.z += u * c1.x; aLo.w += u * c1.y;
            aHi.x += u * c2.x; aHi.y += u * c2.y; aHi.z += u * c3.x; aHi.w += u * c3.y;
        }
        __syncthreads();
    }
    aLo.x += bLo.x; aLo.y += bLo.y; aLo.z += bLo.z; aLo.w += bLo.w;
    aHi.x += bHi.x; aHi.y += bHi.y; aHi.z += bHi.z; aHi.w += bHi.w;

    // combine group 1 into group 0
    if (g == 1) {
        float4* c4p = (float4*)(sComb + lane * 8);
        c4p[0] = aLo; c4p[1] = aHi;
    }
    __syncthreads();
    if (g == 0) {
        const float4* c4p = (const float4*)(sComb + lane * 8);
        float4 pLo = c4p[0], pHi = c4p[1];
        aLo.x += pLo.x; aLo.y += pLo.y; aLo.z += pLo.z; aLo.w += pLo.w;
        aHi.x += pHi.x; aHi.y += pHi.y; aHi.z += pHi.z; aHi.w += pHi.w;

        int d0 = 8 * (lane & 7);
        float4 bb0 = ((const float4*)bias)[2 * (lane & 7)];
        float4 bb1 = ((const float4*)bias)[2 * (lane & 7) + 1];
        aLo.x = fmaxf(aLo.x + bb0.x, 0.f);
        aLo.y = fmaxf(aLo.y + bb0.y, 0.f);
        aLo.z = fmaxf(aLo.z + bb0.z, 0.f);
        aLo.w = fmaxf(aLo.w + bb0.w, 0.f);
        aHi.x = fmaxf(aHi.x + bb1.x, 0.f);
        aHi.y = fmaxf(aHi.y + bb1.y, 0.f);
        aHi.z = fmaxf(aHi.z + bb1.z, 0.f);
        aHi.w = fmaxf(aHi.w + bb1.w, 0.f);

        // fc-dot over this thread's 8 dims (fp32 x)
        float sp = aLo.x * fcW[3 * d0 + fc_off]
                 + aLo.y * fcW[3 * (d0 + 1) + fc_off]
                 + aLo.z * fcW[3 * (d0 + 2) + fc_off]
                 + aLo.w * fcW[3 * (d0 + 3) + fc_off]
                 + aHi.x * fcW[3 * (d0 + 4) + fc_off]
                 + aHi.y * fcW[3 * (d0 + 5) + fc_off]
                 + aHi.z * fcW[3 * (d0 + 6) + fc_off]
                 + aHi.w * fcW[3 * (d0 + 7) + fc_off];
#pragma unroll
        for (int off = 4; off; off >>= 1) sp += __shfl_xor_sync(0xffffffffu, sp, off);
        if ((lane & 7) == 0) {
            size_t idx = (size_t)n * 8 + (lane >> 3);
            g_s[idx] = accum ? (g_s[idx] + sp) : sp;
        }

        if (Wn) {      // stage fp32 x for the epilogue GEMM
            int b = lane >> 3;
            float* xp = sX + b * 64 + d0;
            xp[0] = aLo.x; xp[1] = aLo.y; xp[2] = aLo.z; xp[3] = aLo.w;
            xp[4] = aHi.x; xp[5] = aHi.y; xp[6] = aHi.z; xp[7] = aHi.w;
        }
    }

    // epilogue GEMM: hout16[n][b][f] = sum_k x[b][k] * Wn[k][f]
    if (Wn) {
        __syncthreads();
        int b = t >> 4, q = t & 15;                // output halfs 4q..4q+3
        const float* xrow = sX + b * 64;
        float4 o = make_float4(0.f, 0.f, 0.f, 0.f);
#pragma unroll 8
        for (int k = 0; k < 64; k++) {
            float a = xrow[k];
            float4 w = ((const float4*)sW)[k * 16 + q];
            o.x += a * w.x; o.y += a * w.y; o.z += a * w.z; o.w += a * w.w;
        }
        Half4 pk;
        pk.h[0] = __floats2half2_rn(o.x, o.y);
        pk.h[1] = __floats2half2_rn(o.z, o.w);
        ((uint2*)hout16)[(size_t)n * 128 + b * 16 + q] = pk.u;
    }
}

// ------------------- pathway pooled mean via CSR (deterministic, double) ----
__global__ void __launch_bounds__(256) pool_kernel(const float* __restrict__ fcb) {
    __shared__ double sh[256];
    int c = blockIdx.x;
    int tid = threadIdx.x;
    int b = tid & 7;
    int i = tid >> 3;
    int e0 = g_rowptr2[c], e1 = g_rowptr2[c + 1];
    double acc = 0.0;
    for (int e = e0 + i; e < e1; e += 32) {
        int r = g_csr2_row[e];
        acc += (double)g_s[(size_t)r * 8 + b];
    }
    sh[tid] = acc;
    __syncthreads();
    for (int off = 128; off >= 8; off >>= 1) {
        if (tid < off) sh[tid] += sh[tid + off];
        __syncthreads();
    }
    if (tid < 8) {
        double cnt = (double)(e1 - e0);
        if (cnt < 1.0) cnt = 1.0;
        g_pool[c * 8 + tid] = (float)(sh[tid] / cnt + (double)fcb[0]);
    }
}

// ------------------- MLP head ------------------------------------------------
__global__ void __launch_bounds__(128) mlp1_kernel(const float* __restrict__ l1W) {
    int b = blockIdx.x & 7;
    int chunk = blockIdx.x >> 3;
    int j = threadIdx.x;
    int c0 = chunk * 125, c1 = c0 + 125;
    float acc = 0.f;
    for (int c = c0; c < c1; c++)
        acc += g_pool[c * 8 + b] * l1W[c * HFC + j];
    g_part[((size_t)chunk * 8 + b) * HFC + j] = acc;
}

__global__ void __launch_bounds__(128) mlp2_kernel(
        const float* __restrict__ l1b, const float* __restrict__ l2W,
        const float* __restrict__ l2b, float* __restrict__ out) {
    __shared__ double sz0[128], sz1[128];
    int b = blockIdx.x, j = threadIdx.x;
    double hv = (double)l1b[j];
#pragma unroll
    for (int k = 0; k < 8; k++) hv += (double)g_part[((size_t)k * 8 + b) * HFC + j];
    if (hv < 0.0) hv = 0.0;
    sz0[j] = hv * (double)l2W[j * 2];
    sz1[j] = hv * (double)l2W[j * 2 + 1];
    __syncthreads();
    for (int off = 64; off; off >>= 1) {
        if (j < off) { sz0[j] += sz0[j + off]; sz1[j] += sz1[j + off]; }
        __syncthreads();
    }
    if (j == 0) {
        double z0 = sz0[0] + (double)l2b[0];
        double z1 = sz1[0] + (double)l2b[1];
        double m = z0 > z1 ? z0 : z1;
        double lse = m + log(exp(z0 - m) + exp(z1 - m));
        out[b * 2]     = (float)(z0 - lse);
        out[b * 2 + 1] = (float)(z1 - lse);
    }
}

// ------------------- launch --------------------------------------------------
extern "C" void kernel_launch(void* const* d_in, const int* in_sizes, int n_in,
                              void* d_out, int out_size) {
    const float* x    = (const float*)d_in[0];
    const int*   ei   = (const int*)  d_in[2];
    const int*   prow = (const int*)  d_in[3];
    const int*   pcol = (const int*)  d_in[4];
    const float* W1   = (const float*)d_in[5];
    const float* b1   = (const float*)d_in[6];
    const float* W2   = (const float*)d_in[7];
    const float* b2   = (const float*)d_in[8];
    const float* W3   = (const float*)d_in[9];
    const float* b3   = (const float*)d_in[10];
    const float* fcW  = (const float*)d_in[11];
    const float* fcb  = (const float*)d_in[12];
    const float* l1W  = (const float*)d_in[13];
    const float* l1b  = (const float*)d_in[14];
    const float* l2W  = (const float*)d_in[15];
    const float* l2b  = (const float*)d_in[16];
    float* out = (float*)d_out;

    int E = in_sizes[2] / 2;
    int P = in_sizes[3];
    int EP = E > P ? E : P;

    int gemm_blocks = (NROWS + 63) / 64;                      // 1892

    // launch order (ncu captures idx 3 = gemm1):
    zero_kernel<<<(N_GENES + 255) / 256, 256>>>();                              // 0
    degrees_kernel<<<(EP + 255) / 256, 256>>>(ei, E, pcol, P);                  // 1
    scans_kernel<<<2, 1024>>>();                                                // 2
    gemm_kernel<<<gemm_blocks, 256>>>(x, W1, g_hA);                             // 3 <- profiled
    fills_kernel<<<(EP + 255) / 256, 256>>>(ei, E, prow, pcol, P);              // 4
    // ping-pong: A -> B -> A -> (read A, no write)  — NO in-place races
    agg_kernel<<<N_GENES, 128>>>(g_hA, b1, W2, g_hB, fcW, 0, 0);                // 5
    agg_kernel<<<N_GENES, 128>>>(g_hB, b2, W3, g_hA, fcW, 1, 1);                // 6
    agg_kernel<<<N_GENES, 128>>>(g_hA, b3, (const float*)0, (__half*)0,
                                 fcW, 2, 1);                                    // 7
    pool_kernel<<<NCMT, 256>>>(fcb);                                            // 8
    mlp1_kernel<<<64, HFC>>>(l1W);                                              // 9
    mlp2_kernel<<<BS, HFC>>>(l1b, l2W, l2b, out);                               // 10
}